// round 1
// baseline (speedup 1.0000x reference)
#include <cuda_runtime.h>
#include <cuda_bf16.h>
#include <math.h>

// ---------------------------------------------------------------------------
// Drugemb: 2-layer GCN + WeightedSumAndMax readout + 2-layer MLP head.
// Strategy: build CSR (dst-sorted) per launch -> atomic-free aggregation,
// fused dual-GEMM (gcn + residual) per layer with W/Wr in SMEM,
// block-per-graph segmented readout (graph_ids sorted), MLP writes directly
// into remapped output rows (zero rows at idx_wo_smiles).
// ---------------------------------------------------------------------------

#define NODE_F 74
#define HID 128
#define DIM 256

#define N_MAX 131072
#define E_MAX 524288
#define G_MAX 8192

// ---- scratch (static __device__; no allocation allowed) ----
__device__ float g_norm_s[N_MAX];
__device__ float g_norm_d[N_MAX];
__device__ int   g_outdeg[N_MAX];
__device__ int   g_indeg[N_MAX];
__device__ int   g_fill[N_MAX];
__device__ int   g_rowptr[N_MAX + 1];
__device__ int   g_csr_src[E_MAX];
__device__ float g_agg[(size_t)N_MAX * HID];   // reused: layer1 (stride 74), layer2 (stride 128)
__device__ float g_h1[(size_t)N_MAX * HID];
__device__ float g_h2[(size_t)N_MAX * HID];
__device__ float g_aw[N_MAX];
__device__ int   g_gstart[G_MAX + 1];
__device__ float g_gfeat[(size_t)G_MAX * 2 * HID];
__device__ float g_hidden[(size_t)G_MAX * HID];

// ---------------------------------------------------------------------------
__global__ void k_zero3(int n) {
    int i = blockIdx.x * blockDim.x + threadIdx.x;
    if (i < n) { g_outdeg[i] = 0; g_indeg[i] = 0; g_fill[i] = 0; }
}

__global__ void k_zero_out(float* __restrict__ o, int n) {
    int i = blockIdx.x * blockDim.x + threadIdx.x;
    if (i < n) o[i] = 0.0f;
}

__global__ void k_deg(const int* __restrict__ src, const int* __restrict__ dst, int E) {
    int e = blockIdx.x * blockDim.x + threadIdx.x;
    if (e < E) {
        atomicAdd(&g_outdeg[src[e]], 1);
        atomicAdd(&g_indeg[dst[e]], 1);
    }
}

__global__ void k_norm(int n) {
    int i = blockIdx.x * blockDim.x + threadIdx.x;
    if (i < n) {
        g_norm_s[i] = rsqrtf(fmaxf((float)g_outdeg[i], 1.0f));
        g_norm_d[i] = rsqrtf(fmaxf((float)g_indeg[i], 1.0f));
    }
}

// single-block exclusive scan of g_indeg -> g_rowptr (N up to 131072)
__global__ void k_scan(int n, int e_total) {
    __shared__ int wsum[32];
    __shared__ int sh_carry;
    __shared__ int sh_total;
    int tid = threadIdx.x, lane = tid & 31, warp = tid >> 5;
    if (tid == 0) sh_carry = 0;
    __syncthreads();
    for (int base = 0; base < n; base += 1024) {
        int i = base + tid;
        int v = (i < n) ? g_indeg[i] : 0;
        int x = v;
        #pragma unroll
        for (int o = 1; o < 32; o <<= 1) {
            int t = __shfl_up_sync(0xffffffffu, x, o);
            if (lane >= o) x += t;
        }
        if (lane == 31) wsum[warp] = x;
        __syncthreads();
        if (warp == 0) {
            int s2 = wsum[lane];
            int y = s2;
            #pragma unroll
            for (int o = 1; o < 32; o <<= 1) {
                int t = __shfl_up_sync(0xffffffffu, y, o);
                if (lane >= o) y += t;
            }
            wsum[lane] = y - s2;          // exclusive warp offset
            if (lane == 31) sh_total = y; // tile total
        }
        __syncthreads();
        int incl = x + wsum[warp];
        if (i < n) g_rowptr[i] = sh_carry + incl - v;
        __syncthreads();
        if (tid == 0) sh_carry += sh_total;
        __syncthreads();
    }
    if (tid == 0) g_rowptr[n] = e_total;
}

__global__ void k_fill_csr(const int* __restrict__ src, const int* __restrict__ dst, int E) {
    int e = blockIdx.x * blockDim.x + threadIdx.x;
    if (e < E) {
        int d = dst[e];
        int pos = g_rowptr[d] + atomicAdd(&g_fill[d], 1);
        g_csr_src[pos] = src[e];
    }
}

// warp-per-node CSR aggregation: agg[i] = norm_d[i] * sum_{e: dst=i} norm_s[s]*h[s]
template <int F>
__global__ void k_aggregate(const float* __restrict__ hin, float* __restrict__ aggout, int n) {
    int w = (blockIdx.x * blockDim.x + threadIdx.x) >> 5;
    int lane = threadIdx.x & 31;
    if (w >= n) return;
    constexpr int R = (F + 31) / 32;
    float acc[R];
    #pragma unroll
    for (int j = 0; j < R; j++) acc[j] = 0.0f;
    int e0 = g_rowptr[w], e1 = g_rowptr[w + 1];
    for (int e = e0; e < e1; e++) {
        int s = g_csr_src[e];
        float ns = g_norm_s[s];
        const float* row = hin + (size_t)s * F;
        #pragma unroll
        for (int j = 0; j < R; j++) {
            int f = lane + 32 * j;
            if (F % 32 == 0 || f < F) acc[j] += ns * __ldg(&row[f]);
        }
    }
    float nd = g_norm_d[w];
    float* orow = aggout + (size_t)w * F;
    #pragma unroll
    for (int j = 0; j < R; j++) {
        int f = lane + 32 * j;
        if (F % 32 == 0 || f < F) orow[f] = acc[j] * nd;
    }
}

// fused dual GEMM: Out = relu(X@W + b) + relu(Y@Wr + br), Out is N x 128
// block: 64 rows x 128 cols, 256 threads, thread tile 4x8
template <int K>
__global__ void k_dual_gemm(const float* __restrict__ X, const float* __restrict__ Y,
                            const float* __restrict__ W, const float* __restrict__ b,
                            const float* __restrict__ Wr, const float* __restrict__ br,
                            float* __restrict__ Out, int n) {
    extern __shared__ float sm[];
    constexpr int BM = 64;
    constexpr int LDX = K + 1;
    float* sW  = sm;                 // K*128
    float* sWr = sW + K * 128;       // K*128
    float* sX  = sWr + K * 128;      // BM*LDX
    float* sY  = sX + BM * LDX;      // BM*LDX
    int tid = threadIdx.x;
    for (int i = tid; i < K * 128; i += 256) { sW[i] = W[i]; sWr[i] = Wr[i]; }
    int row0 = blockIdx.x * BM;
    for (int i = tid; i < BM * K; i += 256) {
        int r = i / K, k = i - r * K;
        int gr = row0 + r;
        float xv = 0.0f, yv = 0.0f;
        if (gr < n) {
            xv = X[(size_t)gr * K + k];
            yv = Y[(size_t)gr * K + k];
        }
        sX[r * LDX + k] = xv;
        sY[r * LDX + k] = yv;
    }
    __syncthreads();

    int tx = tid & 15;   // col group: cols [tx*8, tx*8+8)
    int ty = tid >> 4;   // row group: rows [ty*4, ty*4+4)
    float acc1[4][8], acc2[4][8];
    #pragma unroll
    for (int i = 0; i < 4; i++)
        #pragma unroll
        for (int j = 0; j < 8; j++) { acc1[i][j] = 0.0f; acc2[i][j] = 0.0f; }

    #pragma unroll 2
    for (int k = 0; k < K; k++) {
        float xf[4], yf[4];
        #pragma unroll
        for (int i = 0; i < 4; i++) {
            xf[i] = sX[(ty * 4 + i) * LDX + k];
            yf[i] = sY[(ty * 4 + i) * LDX + k];
        }
        float4 w0 = *(const float4*)&sW[k * 128 + tx * 8];
        float4 w1 = *(const float4*)&sW[k * 128 + tx * 8 + 4];
        float4 r0 = *(const float4*)&sWr[k * 128 + tx * 8];
        float4 r1 = *(const float4*)&sWr[k * 128 + tx * 8 + 4];
        float wv[8] = {w0.x, w0.y, w0.z, w0.w, w1.x, w1.y, w1.z, w1.w};
        float rv[8] = {r0.x, r0.y, r0.z, r0.w, r1.x, r1.y, r1.z, r1.w};
        #pragma unroll
        for (int i = 0; i < 4; i++)
            #pragma unroll
            for (int j = 0; j < 8; j++) {
                acc1[i][j] += xf[i] * wv[j];
                acc2[i][j] += yf[i] * rv[j];
            }
    }

    #pragma unroll
    for (int i = 0; i < 4; i++) {
        int gr = row0 + ty * 4 + i;
        if (gr < n) {
            #pragma unroll
            for (int j = 0; j < 8; j++) {
                int c = tx * 8 + j;
                float v = fmaxf(acc1[i][j] + __ldg(&b[c]), 0.0f) +
                          fmaxf(acc2[i][j] + __ldg(&br[c]), 0.0f);
                Out[(size_t)gr * 128 + c] = v;
            }
        }
    }
}

// aw[i] = sigmoid(h2[i] . w_atom + b_atom); warp per node
__global__ void k_aw(const float* __restrict__ wa, const float* __restrict__ ba, int n) {
    int w = (blockIdx.x * blockDim.x + threadIdx.x) >> 5;
    int lane = threadIdx.x & 31;
    if (w >= n) return;
    const float* row = g_h2 + (size_t)w * HID;
    float d = 0.0f;
    #pragma unroll
    for (int j = 0; j < 4; j++) d += row[lane + 32 * j] * __ldg(&wa[lane + 32 * j]);
    #pragma unroll
    for (int o = 16; o > 0; o >>= 1) d += __shfl_xor_sync(0xffffffffu, d, o);
    if (lane == 0) g_aw[w] = 1.0f / (1.0f + expf(-(d + ba[0])));
}

__global__ void k_gbound(const int* __restrict__ gid, int n, int G) {
    int i = blockIdx.x * blockDim.x + threadIdx.x;
    if (i < n) {
        int g = gid[i];
        if (i == 0 || gid[i - 1] != g) g_gstart[g] = i;
        if (i == n - 1) g_gstart[G] = n;
    }
}

// block per graph, thread per feature: weighted sum + max
__global__ void k_readout(int G) {
    int g = blockIdx.x;
    int f = threadIdx.x;  // 128
    if (g >= G) return;
    int s = g_gstart[g], e = g_gstart[g + 1];
    float sum = 0.0f, mx = -3.4e38f;
    for (int i = s; i < e; i++) {
        float v = g_h2[(size_t)i * HID + f];
        sum += g_aw[i] * v;
        mx = fmaxf(mx, v);
    }
    g_gfeat[(size_t)g * 2 * HID + f] = sum;
    g_gfeat[(size_t)g * 2 * HID + HID + f] = mx;
}

// hidden = relu(gfeat @ Wp1 + bp1); 8 graphs per block, 128 threads (col = tid)
__global__ void k_mlp1(const float* __restrict__ Wp1, const float* __restrict__ bp1, int G) {
    int g0 = blockIdx.x * 8;
    int tid = threadIdx.x;
    float acc[8];
    #pragma unroll
    for (int j = 0; j < 8; j++) acc[j] = 0.0f;
    for (int k = 0; k < 2 * HID; k++) {
        float w = __ldg(&Wp1[k * HID + tid]);
        #pragma unroll
        for (int j = 0; j < 8; j++) {
            int g = g0 + j;
            if (g < G) acc[j] += g_gfeat[(size_t)g * 2 * HID + k] * w;
        }
    }
    float bb = __ldg(&bp1[tid]);
    #pragma unroll
    for (int j = 0; j < 8; j++) {
        int g = g0 + j;
        if (g < G) g_hidden[(size_t)g * HID + tid] = fmaxf(acc[j] + bb, 0.0f);
    }
}

// latent = hidden @ Wp2 + bp2, scattered into d_out at remapped row positions
__global__ void k_mlp2(const float* __restrict__ Wp2, const float* __restrict__ bp2,
                       const int* __restrict__ idx, int Kidx, int G,
                       float* __restrict__ out) {
    int g0 = blockIdx.x * 8;
    int tid = threadIdx.x;  // 256
    float acc[8];
    #pragma unroll
    for (int j = 0; j < 8; j++) acc[j] = 0.0f;
    for (int k = 0; k < HID; k++) {
        float w = __ldg(&Wp2[k * DIM + tid]);
        #pragma unroll
        for (int j = 0; j < 8; j++) {
            int g = g0 + j;
            if (g < G) acc[j] += g_hidden[(size_t)g * HID + k] * w;
        }
    }
    float bb = __ldg(&bp2[tid]);
    #pragma unroll
    for (int j = 0; j < 8; j++) {
        int g = g0 + j;
        if (g < G) {
            // map latent row g -> output position (skip zero rows; idx sorted asc)
            int p = g;
            for (int t = 0; t < Kidx; t++) {
                if (__ldg(&idx[t]) <= p) p++;
            }
            out[(size_t)p * DIM + tid] = acc[j] + bb;
        }
    }
}

// ---------------------------------------------------------------------------
extern "C" void kernel_launch(void* const* d_in, const int* in_sizes, int n_in,
                              void* d_out, int out_size) {
    const float* node_feats = (const float*)d_in[0];
    // d_in[1] edge_feats: unused by GCN
    const float* W1  = (const float*)d_in[2];
    const float* b1  = (const float*)d_in[3];
    const float* Wr1 = (const float*)d_in[4];
    const float* br1 = (const float*)d_in[5];
    const float* W2  = (const float*)d_in[6];
    const float* b2  = (const float*)d_in[7];
    const float* Wr2 = (const float*)d_in[8];
    const float* br2 = (const float*)d_in[9];
    const float* w_atom = (const float*)d_in[10];
    const float* b_atom = (const float*)d_in[11];
    const float* Wp1 = (const float*)d_in[12];
    const float* bp1 = (const float*)d_in[13];
    const float* Wp2 = (const float*)d_in[14];
    const float* bp2 = (const float*)d_in[15];
    const int* src = (const int*)d_in[16];
    const int* dst = (const int*)d_in[17];
    const int* graph_ids = (const int*)d_in[18];
    const int* idx_wo = (const int*)d_in[19];
    float* out = (float*)d_out;

    int N = in_sizes[0] / NODE_F;
    int E = in_sizes[16];
    int Kidx = in_sizes[19];
    int total = out_size / DIM;
    int G = total - Kidx;

    // device pointers for scratch symbols consumed as kernel args
    float *p_agg, *p_h1, *p_h2;
    cudaGetSymbolAddress((void**)&p_agg, g_agg);
    cudaGetSymbolAddress((void**)&p_h1, g_h1);
    cudaGetSymbolAddress((void**)&p_h2, g_h2);

    // smem attributes (idempotent)
    const int SMEM74 = (2 * 74 * 128 + 2 * 64 * 75) * 4;    // 114176
    const int SMEM128 = (2 * 128 * 128 + 2 * 64 * 129) * 4; // 197120
    cudaFuncSetAttribute(k_dual_gemm<74>, cudaFuncAttributeMaxDynamicSharedMemorySize, SMEM74);
    cudaFuncSetAttribute(k_dual_gemm<128>, cudaFuncAttributeMaxDynamicSharedMemorySize, SMEM128);

    int tb = 256;
    int gN = (N + tb - 1) / tb;
    int gE = (E + tb - 1) / tb;
    int gW = (N + 7) / 8;  // warp-per-node kernels (256 threads = 8 warps)

    // 1. degrees + norms + CSR
    k_zero3<<<gN, tb>>>(N);
    k_deg<<<gE, tb>>>(src, dst, E);
    k_norm<<<gN, tb>>>(N);
    k_scan<<<1, 1024>>>(N, E);
    k_fill_csr<<<gE, tb>>>(src, dst, E);

    // 2. layer 1: aggregate 74-dim, dual GEMM -> h1
    k_aggregate<74><<<gW, tb>>>(node_feats, p_agg, N);
    k_dual_gemm<74><<<(N + 63) / 64, 256, SMEM74>>>(p_agg, node_feats, W1, b1, Wr1, br1, p_h1, N);

    // 3. layer 2: aggregate 128-dim, dual GEMM -> h2
    k_aggregate<128><<<gW, tb>>>(p_h1, p_agg, N);
    k_dual_gemm<128><<<(N + 63) / 64, 256, SMEM128>>>(p_agg, p_h1, W2, b2, Wr2, br2, p_h2, N);

    // 4. readout
    k_aw<<<gW, tb>>>(w_atom, b_atom, N);
    k_gbound<<<gN, tb>>>(graph_ids, N, G);
    k_readout<<<G, HID>>>(G);

    // 5. MLP head + output (zero rows at idx_wo_smiles)
    k_zero_out<<<(total * DIM + tb - 1) / tb, tb>>>(out, total * DIM);
    k_mlp1<<<(G + 7) / 8, HID>>>(Wp1, bp1, G);
    k_mlp2<<<(G + 7) / 8, DIM>>>(Wp2, bp2, idx_wo, Kidx, G, out);
}

// round 2
// speedup vs baseline: 1.1314x; 1.1314x over previous
#include <cuda_runtime.h>
#include <cuda_bf16.h>
#include <math.h>

// ---------------------------------------------------------------------------
// Drugemb: 2-layer GCN + WeightedSumAndMax readout + 2-layer MLP head.
// R2: multi-block scan (was 87us single-block), FFMA2 (fma.rn.f32x2) dual-GEMM,
// float4 aggregation for 128-dim layer, zero only the K empty output rows.
// ---------------------------------------------------------------------------

#define NODE_F 74
#define HID 128
#define DIM 256

#define N_MAX 131072
#define E_MAX 524288
#define G_MAX 8192
#define SCAN_TPB 1024

typedef unsigned long long u64;

// ---- scratch (static __device__; no allocation allowed) ----
__device__ float g_norm_s[N_MAX];
__device__ float g_norm_d[N_MAX];
__device__ int   g_outdeg[N_MAX];
__device__ int   g_indeg[N_MAX];
__device__ int   g_fill[N_MAX];
__device__ int   g_rowptr[N_MAX + 1];
__device__ int   g_blksum[N_MAX / SCAN_TPB + 2];
__device__ int   g_csr_src[E_MAX];
__device__ float g_agg[(size_t)N_MAX * HID];
__device__ float g_h1[(size_t)N_MAX * HID];
__device__ float g_h2[(size_t)N_MAX * HID];
__device__ float g_aw[N_MAX];
__device__ int   g_gstart[G_MAX + 1];
__device__ float g_gfeat[(size_t)G_MAX * 2 * HID];
__device__ float g_hidden[(size_t)G_MAX * HID];

// ---- f32x2 helpers ----
__device__ __forceinline__ u64 pack2dup(float v) {
    u64 r; asm("mov.b64 %0,{%1,%1};" : "=l"(r) : "f"(v)); return r;
}
__device__ __forceinline__ void fma2(u64& d, u64 a, u64 b) {
    asm("fma.rn.f32x2 %0, %1, %2, %0;" : "+l"(d) : "l"(a), "l"(b));
}
__device__ __forceinline__ void unpack2(u64 v, float& lo, float& hi) {
    asm("mov.b64 {%0,%1}, %2;" : "=f"(lo), "=f"(hi) : "l"(v));
}

// ---------------------------------------------------------------------------
__global__ void k_zero3(int n) {
    int i = blockIdx.x * blockDim.x + threadIdx.x;
    if (i < n) { g_outdeg[i] = 0; g_indeg[i] = 0; g_fill[i] = 0; }
}

__global__ void k_zero_rows(const int* __restrict__ idx, float* __restrict__ o) {
    // one block per empty row, 256 threads = DIM
    int r = idx[blockIdx.x];
    o[(size_t)r * DIM + threadIdx.x] = 0.0f;
}

__global__ void k_deg(const int* __restrict__ src, const int* __restrict__ dst, int E) {
    int e = blockIdx.x * blockDim.x + threadIdx.x;
    if (e < E) {
        atomicAdd(&g_outdeg[src[e]], 1);
        atomicAdd(&g_indeg[dst[e]], 1);
    }
}

__global__ void k_norm(int n) {
    int i = blockIdx.x * blockDim.x + threadIdx.x;
    if (i < n) {
        g_norm_s[i] = rsqrtf(fmaxf((float)g_outdeg[i], 1.0f));
        g_norm_d[i] = rsqrtf(fmaxf((float)g_indeg[i], 1.0f));
    }
}

// ---- 3-phase exclusive scan of g_indeg -> g_rowptr ----
__global__ void k_scan1(int n) {
    __shared__ int wsum[32];
    int tid = threadIdx.x, lane = tid & 31, warp = tid >> 5;
    int i = blockIdx.x * SCAN_TPB + tid;
    int v = (i < n) ? g_indeg[i] : 0;
    int x = v;
    #pragma unroll
    for (int o = 1; o < 32; o <<= 1) {
        int t = __shfl_up_sync(0xffffffffu, x, o);
        if (lane >= o) x += t;
    }
    if (lane == 31) wsum[warp] = x;
    __syncthreads();
    if (warp == 0) {
        int s2 = wsum[lane];
        int y = s2;
        #pragma unroll
        for (int o = 1; o < 32; o <<= 1) {
            int t = __shfl_up_sync(0xffffffffu, y, o);
            if (lane >= o) y += t;
        }
        wsum[lane] = y - s2;
    }
    __syncthreads();
    int incl = x + wsum[warp];
    if (i < n) g_rowptr[i] = incl - v;
    if (tid == SCAN_TPB - 1) g_blksum[blockIdx.x] = incl;
}

__global__ void k_scan2(int nblk, int n, int e_total) {
    // single block; nblk <= 1024
    __shared__ int wsum[32];
    int tid = threadIdx.x, lane = tid & 31, warp = tid >> 5;
    int v = (tid < nblk) ? g_blksum[tid] : 0;
    int x = v;
    #pragma unroll
    for (int o = 1; o < 32; o <<= 1) {
        int t = __shfl_up_sync(0xffffffffu, x, o);
        if (lane >= o) x += t;
    }
    if (lane == 31) wsum[warp] = x;
    __syncthreads();
    if (warp == 0) {
        int s2 = wsum[lane];
        int y = s2;
        #pragma unroll
        for (int o = 1; o < 32; o <<= 1) {
            int t = __shfl_up_sync(0xffffffffu, y, o);
            if (lane >= o) y += t;
        }
        wsum[lane] = y - s2;
    }
    __syncthreads();
    if (tid < nblk) g_blksum[tid] = x + wsum[warp] - v;  // exclusive
    if (tid == 0) g_rowptr[n] = e_total;
}

__global__ void k_scan3(int n) {
    int i = blockIdx.x * SCAN_TPB + threadIdx.x;
    if (i < n) g_rowptr[i] += g_blksum[blockIdx.x];
}

__global__ void k_fill_csr(const int* __restrict__ src, const int* __restrict__ dst, int E) {
    int e = blockIdx.x * blockDim.x + threadIdx.x;
    if (e < E) {
        int d = dst[e];
        int pos = g_rowptr[d] + atomicAdd(&g_fill[d], 1);
        g_csr_src[pos] = src[e];
    }
}

// warp-per-node CSR aggregation, scalar (F=74)
__global__ void k_aggregate74(const float* __restrict__ hin, float* __restrict__ aggout, int n) {
    int w = (blockIdx.x * blockDim.x + threadIdx.x) >> 5;
    int lane = threadIdx.x & 31;
    if (w >= n) return;
    float a0 = 0.0f, a1 = 0.0f, a2 = 0.0f;
    int e0 = g_rowptr[w], e1 = g_rowptr[w + 1];
    for (int e = e0; e < e1; e++) {
        int s = g_csr_src[e];
        float ns = g_norm_s[s];
        const float* row = hin + (size_t)s * NODE_F;
        a0 += ns * __ldg(&row[lane]);
        a1 += ns * __ldg(&row[lane + 32]);
        if (lane < NODE_F - 64) a2 += ns * __ldg(&row[lane + 64]);
    }
    float nd = g_norm_d[w];
    float* orow = aggout + (size_t)w * NODE_F;
    orow[lane] = a0 * nd;
    orow[lane + 32] = a1 * nd;
    if (lane < NODE_F - 64) orow[lane + 64] = a2 * nd;
}

// warp-per-node CSR aggregation, float4 (F=128)
__global__ void k_aggregate128(const float* __restrict__ hin, float* __restrict__ aggout, int n) {
    int w = (blockIdx.x * blockDim.x + threadIdx.x) >> 5;
    int lane = threadIdx.x & 31;
    if (w >= n) return;
    float4 acc = make_float4(0.f, 0.f, 0.f, 0.f);
    int e0 = g_rowptr[w], e1 = g_rowptr[w + 1];
    for (int e = e0; e < e1; e++) {
        int s = g_csr_src[e];
        float ns = g_norm_s[s];
        float4 v = __ldg((const float4*)(hin + (size_t)s * HID) + lane);
        acc.x += ns * v.x; acc.y += ns * v.y; acc.z += ns * v.z; acc.w += ns * v.w;
    }
    float nd = g_norm_d[w];
    acc.x *= nd; acc.y *= nd; acc.z *= nd; acc.w *= nd;
    ((float4*)(aggout + (size_t)w * HID))[lane] = acc;
}

// fused dual GEMM with f32x2 FMA: Out = relu(X@W + b) + relu(Y@Wr + br)
// block: 64 rows x 128 cols, 256 threads, thread tile 4 rows x 8 cols (4 col-pairs)
template <int K>
__global__ void __launch_bounds__(256, 1)
k_dual_gemm(const float* __restrict__ X, const float* __restrict__ Y,
            const float* __restrict__ W, const float* __restrict__ b,
            const float* __restrict__ Wr, const float* __restrict__ br,
            float* __restrict__ Out, int n) {
    extern __shared__ float sm[];
    constexpr int BM = 64;
    constexpr int LDX = K + 1;
    float* sW  = sm;                 // K*128
    float* sWr = sW + K * 128;       // K*128
    float* sX  = sWr + K * 128;      // BM*LDX
    float* sY  = sX + BM * LDX;      // BM*LDX
    int tid = threadIdx.x;
    for (int i = tid; i < K * 128; i += 256) { sW[i] = W[i]; sWr[i] = Wr[i]; }
    int row0 = blockIdx.x * BM;
    for (int i = tid; i < BM * K; i += 256) {
        int r = i / K, k = i - r * K;
        int gr = row0 + r;
        float xv = 0.0f, yv = 0.0f;
        if (gr < n) {
            xv = X[(size_t)gr * K + k];
            yv = Y[(size_t)gr * K + k];
        }
        sX[r * LDX + k] = xv;
        sY[r * LDX + k] = yv;
    }
    __syncthreads();

    int tx = tid & 15;   // col group: cols [tx*8, tx*8+8)
    int ty = tid >> 4;   // row group: rows [ty*4, ty*4+4)
    u64 acc1[4][4], acc2[4][4];
    #pragma unroll
    for (int i = 0; i < 4; i++)
        #pragma unroll
        for (int j = 0; j < 4; j++) { acc1[i][j] = 0ull; acc2[i][j] = 0ull; }

    const ulonglong2* pW  = (const ulonglong2*)(sW  + tx * 8);
    const ulonglong2* pWr = (const ulonglong2*)(sWr + tx * 8);

    #pragma unroll 2
    for (int k = 0; k < K; k++) {
        u64 xd[4], yd[4];
        #pragma unroll
        for (int i = 0; i < 4; i++) {
            xd[i] = pack2dup(sX[(ty * 4 + i) * LDX + k]);
            yd[i] = pack2dup(sY[(ty * 4 + i) * LDX + k]);
        }
        ulonglong2 w01 = pW[k * 32];       // 128 floats = 32 ulonglong2 per k-row
        ulonglong2 w23 = pW[k * 32 + 1];
        ulonglong2 r01 = pWr[k * 32];
        ulonglong2 r23 = pWr[k * 32 + 1];
        u64 wv[4] = {w01.x, w01.y, w23.x, w23.y};
        u64 rv[4] = {r01.x, r01.y, r23.x, r23.y};
        #pragma unroll
        for (int i = 0; i < 4; i++)
            #pragma unroll
            for (int j = 0; j < 4; j++) {
                fma2(acc1[i][j], xd[i], wv[j]);
                fma2(acc2[i][j], yd[i], rv[j]);
            }
    }

    #pragma unroll
    for (int i = 0; i < 4; i++) {
        int gr = row0 + ty * 4 + i;
        if (gr < n) {
            float ov[8];
            #pragma unroll
            for (int j = 0; j < 4; j++) {
                float g0, g1, s0, s1;
                unpack2(acc1[i][j], g0, g1);
                unpack2(acc2[i][j], s0, s1);
                int c = tx * 8 + 2 * j;
                ov[2 * j]     = fmaxf(g0 + __ldg(&b[c]), 0.0f)     + fmaxf(s0 + __ldg(&br[c]), 0.0f);
                ov[2 * j + 1] = fmaxf(g1 + __ldg(&b[c + 1]), 0.0f) + fmaxf(s1 + __ldg(&br[c + 1]), 0.0f);
            }
            float4* dst4 = (float4*)(Out + (size_t)gr * 128 + tx * 8);
            dst4[0] = make_float4(ov[0], ov[1], ov[2], ov[3]);
            dst4[1] = make_float4(ov[4], ov[5], ov[6], ov[7]);
        }
    }
}

// aw[i] = sigmoid(h2[i] . w_atom + b_atom); warp per node
__global__ void k_aw(const float* __restrict__ wa, const float* __restrict__ ba, int n) {
    int w = (blockIdx.x * blockDim.x + threadIdx.x) >> 5;
    int lane = threadIdx.x & 31;
    if (w >= n) return;
    const float* row = g_h2 + (size_t)w * HID;
    float d = 0.0f;
    #pragma unroll
    for (int j = 0; j < 4; j++) d += row[lane + 32 * j] * __ldg(&wa[lane + 32 * j]);
    #pragma unroll
    for (int o = 16; o > 0; o >>= 1) d += __shfl_xor_sync(0xffffffffu, d, o);
    if (lane == 0) g_aw[w] = 1.0f / (1.0f + expf(-(d + ba[0])));
}

__global__ void k_gbound(const int* __restrict__ gid, int n, int G) {
    int i = blockIdx.x * blockDim.x + threadIdx.x;
    if (i < n) {
        int g = gid[i];
        if (i == 0 || gid[i - 1] != g) g_gstart[g] = i;
        if (i == n - 1) g_gstart[G] = n;
    }
}

// block per graph, thread per feature: weighted sum + max
__global__ void k_readout(int G) {
    int g = blockIdx.x;
    int f = threadIdx.x;  // 128
    if (g >= G) return;
    int s = g_gstart[g], e = g_gstart[g + 1];
    float sum = 0.0f, mx = -3.4e38f;
    for (int i = s; i < e; i++) {
        float v = g_h2[(size_t)i * HID + f];
        sum += g_aw[i] * v;
        mx = fmaxf(mx, v);
    }
    g_gfeat[(size_t)g * 2 * HID + f] = sum;
    g_gfeat[(size_t)g * 2 * HID + HID + f] = mx;
}

// hidden = relu(gfeat @ Wp1 + bp1); 8 graphs per block, 128 threads (col = tid)
__global__ void k_mlp1(const float* __restrict__ Wp1, const float* __restrict__ bp1, int G) {
    int g0 = blockIdx.x * 8;
    int tid = threadIdx.x;
    float acc[8];
    #pragma unroll
    for (int j = 0; j < 8; j++) acc[j] = 0.0f;
    for (int k = 0; k < 2 * HID; k++) {
        float w = __ldg(&Wp1[k * HID + tid]);
        #pragma unroll
        for (int j = 0; j < 8; j++) {
            int g = g0 + j;
            if (g < G) acc[j] += g_gfeat[(size_t)g * 2 * HID + k] * w;
        }
    }
    float bb = __ldg(&bp1[tid]);
    #pragma unroll
    for (int j = 0; j < 8; j++) {
        int g = g0 + j;
        if (g < G) g_hidden[(size_t)g * HID + tid] = fmaxf(acc[j] + bb, 0.0f);
    }
}

// latent = hidden @ Wp2 + bp2, scattered into d_out at remapped row positions
__global__ void k_mlp2(const float* __restrict__ Wp2, const float* __restrict__ bp2,
                       const int* __restrict__ idx, int Kidx, int G,
                       float* __restrict__ out) {
    int g0 = blockIdx.x * 8;
    int tid = threadIdx.x;  // 256
    float acc[8];
    #pragma unroll
    for (int j = 0; j < 8; j++) acc[j] = 0.0f;
    for (int k = 0; k < HID; k++) {
        float w = __ldg(&Wp2[k * DIM + tid]);
        #pragma unroll
        for (int j = 0; j < 8; j++) {
            int g = g0 + j;
            if (g < G) acc[j] += g_hidden[(size_t)g * HID + k] * w;
        }
    }
    float bb = __ldg(&bp2[tid]);
    #pragma unroll
    for (int j = 0; j < 8; j++) {
        int g = g0 + j;
        if (g < G) {
            int p = g;
            for (int t = 0; t < Kidx; t++) {
                if (__ldg(&idx[t]) <= p) p++;
            }
            out[(size_t)p * DIM + tid] = acc[j] + bb;
        }
    }
}

// ---------------------------------------------------------------------------
extern "C" void kernel_launch(void* const* d_in, const int* in_sizes, int n_in,
                              void* d_out, int out_size) {
    const float* node_feats = (const float*)d_in[0];
    const float* W1  = (const float*)d_in[2];
    const float* b1  = (const float*)d_in[3];
    const float* Wr1 = (const float*)d_in[4];
    const float* br1 = (const float*)d_in[5];
    const float* W2  = (const float*)d_in[6];
    const float* b2  = (const float*)d_in[7];
    const float* Wr2 = (const float*)d_in[8];
    const float* br2 = (const float*)d_in[9];
    const float* w_atom = (const float*)d_in[10];
    const float* b_atom = (const float*)d_in[11];
    const float* Wp1 = (const float*)d_in[12];
    const float* bp1 = (const float*)d_in[13];
    const float* Wp2 = (const float*)d_in[14];
    const float* bp2 = (const float*)d_in[15];
    const int* src = (const int*)d_in[16];
    const int* dst = (const int*)d_in[17];
    const int* graph_ids = (const int*)d_in[18];
    const int* idx_wo = (const int*)d_in[19];
    float* out = (float*)d_out;

    int N = in_sizes[0] / NODE_F;
    int E = in_sizes[16];
    int Kidx = in_sizes[19];
    int total = out_size / DIM;
    int G = total - Kidx;

    float *p_agg, *p_h1, *p_h2;
    cudaGetSymbolAddress((void**)&p_agg, g_agg);
    cudaGetSymbolAddress((void**)&p_h1, g_h1);
    cudaGetSymbolAddress((void**)&p_h2, g_h2);

    const int SMEM74 = (2 * 74 * 128 + 2 * 64 * 75) * 4;    // 114176
    const int SMEM128 = (2 * 128 * 128 + 2 * 64 * 129) * 4; // 197120
    cudaFuncSetAttribute(k_dual_gemm<74>, cudaFuncAttributeMaxDynamicSharedMemorySize, SMEM74);
    cudaFuncSetAttribute(k_dual_gemm<128>, cudaFuncAttributeMaxDynamicSharedMemorySize, SMEM128);

    int tb = 256;
    int gN = (N + tb - 1) / tb;
    int gE = (E + tb - 1) / tb;
    int gW = (N + 7) / 8;
    int nScanBlk = (N + SCAN_TPB - 1) / SCAN_TPB;

    // 1. degrees + norms + CSR
    k_zero3<<<gN, tb>>>(N);
    k_deg<<<gE, tb>>>(src, dst, E);
    k_norm<<<gN, tb>>>(N);
    k_scan1<<<nScanBlk, SCAN_TPB>>>(N);
    k_scan2<<<1, 1024>>>(nScanBlk, N, E);
    k_scan3<<<nScanBlk, SCAN_TPB>>>(N);
    k_fill_csr<<<gE, tb>>>(src, dst, E);

    // 2. layer 1
    k_aggregate74<<<gW, tb>>>(node_feats, p_agg, N);
    k_dual_gemm<74><<<(N + 63) / 64, 256, SMEM74>>>(p_agg, node_feats, W1, b1, Wr1, br1, p_h1, N);

    // 3. layer 2
    k_aggregate128<<<gW, tb>>>(p_h1, p_agg, N);
    k_dual_gemm<128><<<(N + 63) / 64, 256, SMEM128>>>(p_agg, p_h1, W2, b2, Wr2, br2, p_h2, N);

    // 4. readout
    k_aw<<<gW, tb>>>(w_atom, b_atom, N);
    k_gbound<<<gN, tb>>>(graph_ids, N, G);
    k_readout<<<G, HID>>>(G);

    // 5. MLP head + output (zero rows only at idx_wo_smiles; mlp2 covers the rest)
    if (Kidx > 0) k_zero_rows<<<Kidx, DIM>>>(idx_wo, out);
    k_mlp1<<<(G + 7) / 8, HID>>>(Wp1, bp1, G);
    k_mlp2<<<(G + 7) / 8, DIM>>>(Wp2, bp2, idx_wo, Kidx, G, out);
}

// round 3
// speedup vs baseline: 1.5936x; 1.4086x over previous
#include <cuda_runtime.h>
#include <cuda_bf16.h>
#include <math.h>

// ---------------------------------------------------------------------------
// Drugemb: 2-layer GCN + WeightedSumAndMax readout + 2-layer MLP head.
// R3: dual-GEMMs on tensor cores (mma.sync m16n8k16 bf16, 3-term hi/lo split
// for ~fp32 accuracy). Weights pre-converted to transposed padded bf16 pairs
// once per launch. CSR aggregation + readout unchanged.
// ---------------------------------------------------------------------------

#define NODE_F 74
#define HID 128
#define DIM 256

#define N_MAX 131072
#define E_MAX 524288
#define G_MAX 8192
#define SCAN_TPB 1024

typedef unsigned int u32;
typedef __nv_bfloat16 bf16;

// layer1: K=74 -> Kceil=80, Kp=88 ((Kp/2)%32==12: conflict-free pattern)
// layer2: K=128 -> Kceil=128, Kp=136 ((Kp/2)%32==4)
#define KP1 88
#define KP2 136
#define WSEG1 (128 * KP1)   // 11264 elems per weight matrix (layer1)
#define WSEG2 (128 * KP2)   // 17408 elems (layer2)

// ---- scratch (static __device__; no allocation allowed) ----
__device__ float g_norm_s[N_MAX];
__device__ float g_norm_d[N_MAX];
__device__ int   g_outdeg[N_MAX];
__device__ int   g_indeg[N_MAX];
__device__ int   g_fill[N_MAX];
__device__ int   g_rowptr[N_MAX + 1];
__device__ int   g_blksum[N_MAX / SCAN_TPB + 2];
__device__ int   g_csr_src[E_MAX];
__device__ float g_agg[(size_t)N_MAX * HID];
__device__ float g_h1[(size_t)N_MAX * HID];
__device__ float g_h2[(size_t)N_MAX * HID];
__device__ float g_aw[N_MAX];
__device__ int   g_gstart[G_MAX + 1];
__device__ float g_gfeat[(size_t)G_MAX * 2 * HID];
__device__ float g_hidden[(size_t)G_MAX * HID];
__device__ bf16  g_wt[4 * WSEG1 + 4 * WSEG2];  // whi,wlo,rhi,rlo per layer

// ---------------------------------------------------------------------------
__global__ void k_zero3(int n) {
    int i = blockIdx.x * blockDim.x + threadIdx.x;
    if (i < n) { g_outdeg[i] = 0; g_indeg[i] = 0; g_fill[i] = 0; }
}

__global__ void k_zero_rows(const int* __restrict__ idx, float* __restrict__ o) {
    int r = idx[blockIdx.x];
    o[(size_t)r * DIM + threadIdx.x] = 0.0f;
}

__global__ void k_deg(const int* __restrict__ src, const int* __restrict__ dst, int E) {
    int e = blockIdx.x * blockDim.x + threadIdx.x;
    if (e < E) {
        atomicAdd(&g_outdeg[src[e]], 1);
        atomicAdd(&g_indeg[dst[e]], 1);
    }
}

__global__ void k_norm(int n) {
    int i = blockIdx.x * blockDim.x + threadIdx.x;
    if (i < n) {
        g_norm_s[i] = rsqrtf(fmaxf((float)g_outdeg[i], 1.0f));
        g_norm_d[i] = rsqrtf(fmaxf((float)g_indeg[i], 1.0f));
    }
}

// ---- weight conversion: W[K][128] fp32 -> wt[n*Kp+k] bf16 hi/lo, zero pad ----
__global__ void k_convw(const float* __restrict__ W, const float* __restrict__ Wr,
                        int K, int Kp, bf16* __restrict__ base) {
    int i = blockIdx.x * blockDim.x + threadIdx.x;
    int seg = 128 * Kp;
    if (i >= 2 * seg) return;
    const float* S = (i < seg) ? W : Wr;
    bf16* hi = (i < seg) ? base : base + 2 * seg;
    bf16* lo = hi + seg;
    int j = (i < seg) ? i : i - seg;
    int n = j / Kp, k = j - n * Kp;
    float v = (k < K) ? S[k * 128 + n] : 0.0f;
    bf16 h = __float2bfloat16_rn(v);
    bf16 l = __float2bfloat16_rn(v - __bfloat162float(h));
    hi[j] = h;
    lo[j] = l;
}

// ---- 3-phase exclusive scan of g_indeg -> g_rowptr ----
__global__ void k_scan1(int n) {
    __shared__ int wsum[32];
    int tid = threadIdx.x, lane = tid & 31, warp = tid >> 5;
    int i = blockIdx.x * SCAN_TPB + tid;
    int v = (i < n) ? g_indeg[i] : 0;
    int x = v;
    #pragma unroll
    for (int o = 1; o < 32; o <<= 1) {
        int t = __shfl_up_sync(0xffffffffu, x, o);
        if (lane >= o) x += t;
    }
    if (lane == 31) wsum[warp] = x;
    __syncthreads();
    if (warp == 0) {
        int s2 = wsum[lane];
        int y = s2;
        #pragma unroll
        for (int o = 1; o < 32; o <<= 1) {
            int t = __shfl_up_sync(0xffffffffu, y, o);
            if (lane >= o) y += t;
        }
        wsum[lane] = y - s2;
    }
    __syncthreads();
    int incl = x + wsum[warp];
    if (i < n) g_rowptr[i] = incl - v;
    if (tid == SCAN_TPB - 1) g_blksum[blockIdx.x] = incl;
}

__global__ void k_scan2(int nblk, int n, int e_total) {
    __shared__ int wsum[32];
    int tid = threadIdx.x, lane = tid & 31, warp = tid >> 5;
    int v = (tid < nblk) ? g_blksum[tid] : 0;
    int x = v;
    #pragma unroll
    for (int o = 1; o < 32; o <<= 1) {
        int t = __shfl_up_sync(0xffffffffu, x, o);
        if (lane >= o) x += t;
    }
    if (lane == 31) wsum[warp] = x;
    __syncthreads();
    if (warp == 0) {
        int s2 = wsum[lane];
        int y = s2;
        #pragma unroll
        for (int o = 1; o < 32; o <<= 1) {
            int t = __shfl_up_sync(0xffffffffu, y, o);
            if (lane >= o) y += t;
        }
        wsum[lane] = y - s2;
    }
    __syncthreads();
    if (tid < nblk) g_blksum[tid] = x + wsum[warp] - v;
    if (tid == 0) g_rowptr[n] = e_total;
}

__global__ void k_scan3(int n) {
    int i = blockIdx.x * SCAN_TPB + threadIdx.x;
    if (i < n) g_rowptr[i] += g_blksum[blockIdx.x];
}

__global__ void k_fill_csr(const int* __restrict__ src, const int* __restrict__ dst, int E) {
    int e = blockIdx.x * blockDim.x + threadIdx.x;
    if (e < E) {
        int d = dst[e];
        int pos = g_rowptr[d] + atomicAdd(&g_fill[d], 1);
        g_csr_src[pos] = src[e];
    }
}

// warp-per-node CSR aggregation, scalar (F=74)
__global__ void k_aggregate74(const float* __restrict__ hin, float* __restrict__ aggout, int n) {
    int w = (blockIdx.x * blockDim.x + threadIdx.x) >> 5;
    int lane = threadIdx.x & 31;
    if (w >= n) return;
    float a0 = 0.0f, a1 = 0.0f, a2 = 0.0f;
    int e0 = g_rowptr[w], e1 = g_rowptr[w + 1];
    for (int e = e0; e < e1; e++) {
        int s = g_csr_src[e];
        float ns = g_norm_s[s];
        const float* row = hin + (size_t)s * NODE_F;
        a0 += ns * __ldg(&row[lane]);
        a1 += ns * __ldg(&row[lane + 32]);
        if (lane < NODE_F - 64) a2 += ns * __ldg(&row[lane + 64]);
    }
    float nd = g_norm_d[w];
    float* orow = aggout + (size_t)w * NODE_F;
    orow[lane] = a0 * nd;
    orow[lane + 32] = a1 * nd;
    if (lane < NODE_F - 64) orow[lane + 64] = a2 * nd;
}

// warp-per-node CSR aggregation, float4 (F=128)
__global__ void k_aggregate128(const float* __restrict__ hin, float* __restrict__ aggout, int n) {
    int w = (blockIdx.x * blockDim.x + threadIdx.x) >> 5;
    int lane = threadIdx.x & 31;
    if (w >= n) return;
    float4 acc = make_float4(0.f, 0.f, 0.f, 0.f);
    int e0 = g_rowptr[w], e1 = g_rowptr[w + 1];
    for (int e = e0; e < e1; e++) {
        int s = g_csr_src[e];
        float ns = g_norm_s[s];
        float4 v = __ldg((const float4*)(hin + (size_t)s * HID) + lane);
        acc.x += ns * v.x; acc.y += ns * v.y; acc.z += ns * v.z; acc.w += ns * v.w;
    }
    float nd = g_norm_d[w];
    acc.x *= nd; acc.y *= nd; acc.z *= nd; acc.w *= nd;
    ((float4*)(aggout + (size_t)w * HID))[lane] = acc;
}

// ---- tensor-core dual GEMM ----
__device__ __forceinline__ void mma16816(float* c, const u32* a, const u32* b) {
    asm volatile(
        "mma.sync.aligned.m16n8k16.row.col.f32.bf16.bf16.f32 "
        "{%0,%1,%2,%3}, {%4,%5,%6,%7}, {%8,%9}, {%0,%1,%2,%3};"
        : "+f"(c[0]), "+f"(c[1]), "+f"(c[2]), "+f"(c[3])
        : "r"(a[0]), "r"(a[1]), "r"(a[2]), "r"(a[3]), "r"(b[0]), "r"(b[1]));
}

// Out[N x 128] = relu(X@W + b) + relu(Y@Wr + br)
// Block: 64 rows, 256 threads (8 warps: 4 along M x 2 along N(64 each)).
// wbase: bf16 [whi|wlo|rhi|rlo], each [128][Kp] (n-major, k padded/zeroed).
template <int K, int Kp, int Kceil>
__global__ void __launch_bounds__(256, 1)
k_mma_gemm(const float* __restrict__ X, const float* __restrict__ Y,
           const bf16* __restrict__ wbase,
           const float* __restrict__ b, const float* __restrict__ br,
           float* __restrict__ Out, int n) {
    extern __shared__ char sm_raw[];
    bf16* sW = (bf16*)sm_raw;            // 4*128*Kp (whi,wlo,rhi,rlo)
    bf16* sX = sW + 4 * 128 * Kp;        // 4*64*Kp (xhi,xlo,yhi,ylo)
    int tid = threadIdx.x;
    int row0 = blockIdx.x * 64;

    // 1. copy pre-converted weights (linear, coalesced)
    {
        const uint4* gsrc = (const uint4*)wbase;
        uint4* sdst = (uint4*)sW;
        const int n16 = 4 * 128 * Kp / 8;  // uint4 = 8 bf16
        for (int i = tid; i < n16; i += 256) sdst[i] = gsrc[i];
    }

    // 2. load X/Y tiles, convert fp32 -> bf16 hi/lo
    bf16* sXhi = sX;
    bf16* sXlo = sX + 64 * Kp;
    bf16* sYhi = sX + 128 * Kp;
    bf16* sYlo = sX + 192 * Kp;
    for (int i = tid; i < 64 * K; i += 256) {
        int r = i / K, k = i - r * K;
        int gr = row0 + r;
        float xv = 0.0f, yv = 0.0f;
        if (gr < n) {
            xv = X[(size_t)gr * K + k];
            yv = Y[(size_t)gr * K + k];
        }
        bf16 xh = __float2bfloat16_rn(xv);
        bf16 yh = __float2bfloat16_rn(yv);
        sXhi[r * Kp + k] = xh;
        sXlo[r * Kp + k] = __float2bfloat16_rn(xv - __bfloat162float(xh));
        sYhi[r * Kp + k] = yh;
        sYlo[r * Kp + k] = __float2bfloat16_rn(yv - __bfloat162float(yh));
    }
    if (Kceil > K) {
        for (int i = tid; i < 64 * (Kceil - K); i += 256) {
            int r = i / (Kceil - K), k = K + i % (Kceil - K);
            bf16 z = __float2bfloat16_rn(0.0f);
            sXhi[r * Kp + k] = z; sXlo[r * Kp + k] = z;
            sYhi[r * Kp + k] = z; sYlo[r * Kp + k] = z;
        }
    }
    __syncthreads();

    // word-indexed views (u32 = 2 bf16)
    const u32* uS = (const u32*)sm_raw;
    const int KW = Kp / 2;                 // words per k-row
    const int W0 = 0;                      // whi
    const int W1 = 64 * Kp;                // wlo   (128*Kp halves = 64*Kp words)
    const int R0 = 128 * Kp;
    const int R1 = 192 * Kp;
    const int XH = 256 * Kp;
    const int XL = XH + 32 * Kp;
    const int YH = XH + 64 * Kp;
    const int YL = XH + 96 * Kp;

    int lane = tid & 31, warp = tid >> 5;
    int wm = warp >> 1;      // 0..3 -> rows wm*16
    int wn = warp & 1;       // 0..1 -> cols wn*64
    int g = lane >> 2, t = lane & 3;

    float acc1[8][4], acc2[8][4];
    #pragma unroll
    for (int j = 0; j < 8; j++)
        #pragma unroll
        for (int q = 0; q < 4; q++) { acc1[j][q] = 0.0f; acc2[j][q] = 0.0f; }

    const int rowA = (wm * 16 + g) * KW;   // word offset of this thread's A row
    constexpr int KSTEPS = Kceil / 16;

    #pragma unroll
    for (int kt = 0; kt < KSTEPS; kt++) {
        const int ko = kt * 8 + t;
        u32 xh[4], xl[4], yh[4], yl[4];
        xh[0] = uS[XH + rowA + ko];          xh[1] = uS[XH + rowA + 4 * Kp + ko];
        xh[2] = uS[XH + rowA + ko + 4];      xh[3] = uS[XH + rowA + 4 * Kp + ko + 4];
        xl[0] = uS[XL + rowA + ko];          xl[1] = uS[XL + rowA + 4 * Kp + ko];
        xl[2] = uS[XL + rowA + ko + 4];      xl[3] = uS[XL + rowA + 4 * Kp + ko + 4];
        yh[0] = uS[YH + rowA + ko];          yh[1] = uS[YH + rowA + 4 * Kp + ko];
        yh[2] = uS[YH + rowA + ko + 4];      yh[3] = uS[YH + rowA + 4 * Kp + ko + 4];
        yl[0] = uS[YL + rowA + ko];          yl[1] = uS[YL + rowA + 4 * Kp + ko];
        yl[2] = uS[YL + rowA + ko + 4];      yl[3] = uS[YL + rowA + 4 * Kp + ko + 4];

        #pragma unroll
        for (int j = 0; j < 8; j++) {
            const int colB = (wn * 64 + j * 8 + g) * KW + ko;
            u32 wh[2], wl[2], rh[2], rl[2];
            wh[0] = uS[W0 + colB]; wh[1] = uS[W0 + colB + 4];
            wl[0] = uS[W1 + colB]; wl[1] = uS[W1 + colB + 4];
            rh[0] = uS[R0 + colB]; rh[1] = uS[R0 + colB + 4];
            rl[0] = uS[R1 + colB]; rl[1] = uS[R1 + colB + 4];
            mma16816(acc1[j], xh, wh);
            mma16816(acc1[j], xh, wl);
            mma16816(acc1[j], xl, wh);
            mma16816(acc2[j], yh, rh);
            mma16816(acc2[j], yh, rl);
            mma16816(acc2[j], yl, rh);
        }
    }

    // epilogue: relu(acc1+b) + relu(acc2+br) -> Out
    int r0 = row0 + wm * 16 + g;
    int r1 = r0 + 8;
    #pragma unroll
    for (int j = 0; j < 8; j++) {
        int c = wn * 64 + j * 8 + 2 * t;
        float b0 = __ldg(&b[c]), b1v = __ldg(&b[c + 1]);
        float q0 = __ldg(&br[c]), q1 = __ldg(&br[c + 1]);
        if (r0 < n) {
            float2 v;
            v.x = fmaxf(acc1[j][0] + b0, 0.0f) + fmaxf(acc2[j][0] + q0, 0.0f);
            v.y = fmaxf(acc1[j][1] + b1v, 0.0f) + fmaxf(acc2[j][1] + q1, 0.0f);
            *(float2*)(Out + (size_t)r0 * 128 + c) = v;
        }
        if (r1 < n) {
            float2 v;
            v.x = fmaxf(acc1[j][2] + b0, 0.0f) + fmaxf(acc2[j][2] + q0, 0.0f);
            v.y = fmaxf(acc1[j][3] + b1v, 0.0f) + fmaxf(acc2[j][3] + q1, 0.0f);
            *(float2*)(Out + (size_t)r1 * 128 + c) = v;
        }
    }
}

// aw[i] = sigmoid(h2[i] . w_atom + b_atom); warp per node
__global__ void k_aw(const float* __restrict__ wa, const float* __restrict__ ba, int n) {
    int w = (blockIdx.x * blockDim.x + threadIdx.x) >> 5;
    int lane = threadIdx.x & 31;
    if (w >= n) return;
    const float* row = g_h2 + (size_t)w * HID;
    float d = 0.0f;
    #pragma unroll
    for (int j = 0; j < 4; j++) d += row[lane + 32 * j] * __ldg(&wa[lane + 32 * j]);
    #pragma unroll
    for (int o = 16; o > 0; o >>= 1) d += __shfl_xor_sync(0xffffffffu, d, o);
    if (lane == 0) g_aw[w] = 1.0f / (1.0f + expf(-(d + ba[0])));
}

__global__ void k_gbound(const int* __restrict__ gid, int n, int G) {
    int i = blockIdx.x * blockDim.x + threadIdx.x;
    if (i < n) {
        int g = gid[i];
        if (i == 0 || gid[i - 1] != g) g_gstart[g] = i;
        if (i == n - 1) g_gstart[G] = n;
    }
}

// block per graph, thread per feature: weighted sum + max
__global__ void k_readout(int G) {
    int g = blockIdx.x;
    int f = threadIdx.x;  // 128
    if (g >= G) return;
    int s = g_gstart[g], e = g_gstart[g + 1];
    float sum = 0.0f, mx = -3.4e38f;
    for (int i = s; i < e; i++) {
        float v = g_h2[(size_t)i * HID + f];
        sum += g_aw[i] * v;
        mx = fmaxf(mx, v);
    }
    g_gfeat[(size_t)g * 2 * HID + f] = sum;
    g_gfeat[(size_t)g * 2 * HID + HID + f] = mx;
}

// hidden = relu(gfeat @ Wp1 + bp1); 8 graphs per block
__global__ void k_mlp1(const float* __restrict__ Wp1, const float* __restrict__ bp1, int G) {
    int g0 = blockIdx.x * 8;
    int tid = threadIdx.x;
    float acc[8];
    #pragma unroll
    for (int j = 0; j < 8; j++) acc[j] = 0.0f;
    for (int k = 0; k < 2 * HID; k++) {
        float w = __ldg(&Wp1[k * HID + tid]);
        #pragma unroll
        for (int j = 0; j < 8; j++) {
            int g = g0 + j;
            if (g < G) acc[j] += g_gfeat[(size_t)g * 2 * HID + k] * w;
        }
    }
    float bb = __ldg(&bp1[tid]);
    #pragma unroll
    for (int j = 0; j < 8; j++) {
        int g = g0 + j;
        if (g < G) g_hidden[(size_t)g * HID + tid] = fmaxf(acc[j] + bb, 0.0f);
    }
}

// latent = hidden @ Wp2 + bp2, scattered into d_out at remapped row positions
__global__ void k_mlp2(const float* __restrict__ Wp2, const float* __restrict__ bp2,
                       const int* __restrict__ idx, int Kidx, int G,
                       float* __restrict__ out) {
    int g0 = blockIdx.x * 8;
    int tid = threadIdx.x;  // 256
    float acc[8];
    #pragma unroll
    for (int j = 0; j < 8; j++) acc[j] = 0.0f;
    for (int k = 0; k < HID; k++) {
        float w = __ldg(&Wp2[k * DIM + tid]);
        #pragma unroll
        for (int j = 0; j < 8; j++) {
            int g = g0 + j;
            if (g < G) acc[j] += g_hidden[(size_t)g * HID + k] * w;
        }
    }
    float bb = __ldg(&bp2[tid]);
    #pragma unroll
    for (int j = 0; j < 8; j++) {
        int g = g0 + j;
        if (g < G) {
            int p = g;
            for (int t = 0; t < Kidx; t++) {
                if (__ldg(&idx[t]) <= p) p++;
            }
            out[(size_t)p * DIM + tid] = acc[j] + bb;
        }
    }
}

// ---------------------------------------------------------------------------
extern "C" void kernel_launch(void* const* d_in, const int* in_sizes, int n_in,
                              void* d_out, int out_size) {
    const float* node_feats = (const float*)d_in[0];
    const float* W1  = (const float*)d_in[2];
    const float* b1  = (const float*)d_in[3];
    const float* Wr1 = (const float*)d_in[4];
    const float* br1 = (const float*)d_in[5];
    const float* W2  = (const float*)d_in[6];
    const float* b2  = (const float*)d_in[7];
    const float* Wr2 = (const float*)d_in[8];
    const float* br2 = (const float*)d_in[9];
    const float* w_atom = (const float*)d_in[10];
    const float* b_atom = (const float*)d_in[11];
    const float* Wp1 = (const float*)d_in[12];
    const float* bp1 = (const float*)d_in[13];
    const float* Wp2 = (const float*)d_in[14];
    const float* bp2 = (const float*)d_in[15];
    const int* src = (const int*)d_in[16];
    const int* dst = (const int*)d_in[17];
    const int* graph_ids = (const int*)d_in[18];
    const int* idx_wo = (const int*)d_in[19];
    float* out = (float*)d_out;

    int N = in_sizes[0] / NODE_F;
    int E = in_sizes[16];
    int Kidx = in_sizes[19];
    int total = out_size / DIM;
    int G = total - Kidx;

    float *p_agg, *p_h1, *p_h2;
    bf16 *p_wt;
    cudaGetSymbolAddress((void**)&p_agg, g_agg);
    cudaGetSymbolAddress((void**)&p_h1, g_h1);
    cudaGetSymbolAddress((void**)&p_h2, g_h2);
    cudaGetSymbolAddress((void**)&p_wt, g_wt);

    // smem: weights 4*128*Kp*2 + tiles 4*64*Kp*2 bytes
    const int SMEM1 = (4 * 128 * KP1 + 4 * 64 * KP1) * 2;  // 135168
    const int SMEM2 = (4 * 128 * KP2 + 4 * 64 * KP2) * 2;  // 208896
    cudaFuncSetAttribute(k_mma_gemm<74, KP1, 80>, cudaFuncAttributeMaxDynamicSharedMemorySize, SMEM1);
    cudaFuncSetAttribute(k_mma_gemm<128, KP2, 128>, cudaFuncAttributeMaxDynamicSharedMemorySize, SMEM2);

    int tb = 256;
    int gN = (N + tb - 1) / tb;
    int gE = (E + tb - 1) / tb;
    int gW = (N + 7) / 8;
    int nScanBlk = (N + SCAN_TPB - 1) / SCAN_TPB;
    int gGemm = (N + 63) / 64;

    // 0. weight conversion (independent of graph work)
    k_convw<<<(2 * 128 * KP1 + tb - 1) / tb, tb>>>(W1, Wr1, 74, KP1, p_wt);
    k_convw<<<(2 * 128 * KP2 + tb - 1) / tb, tb>>>(W2, Wr2, 128, KP2, p_wt + 4 * WSEG1);

    // 1. degrees + norms + CSR
    k_zero3<<<gN, tb>>>(N);
    k_deg<<<gE, tb>>>(src, dst, E);
    k_norm<<<gN, tb>>>(N);
    k_scan1<<<nScanBlk, SCAN_TPB>>>(N);
    k_scan2<<<1, 1024>>>(nScanBlk, N, E);
    k_scan3<<<nScanBlk, SCAN_TPB>>>(N);
    k_fill_csr<<<gE, tb>>>(src, dst, E);

    // 2. layer 1
    k_aggregate74<<<gW, tb>>>(node_feats, p_agg, N);
    k_mma_gemm<74, KP1, 80><<<gGemm, 256, SMEM1>>>(p_agg, node_feats, p_wt, b1, br1, p_h1, N);

    // 3. layer 2
    k_aggregate128<<<gW, tb>>>(p_h1, p_agg, N);
    k_mma_gemm<128, KP2, 128><<<gGemm, 256, SMEM2>>>(p_agg, p_h1, p_wt + 4 * WSEG1, b2, br2, p_h2, N);

    // 4. readout
    k_aw<<<gW, tb>>>(w_atom, b_atom, N);
    k_gbound<<<gN, tb>>>(graph_ids, N, G);
    k_readout<<<G, HID>>>(G);

    // 5. MLP head + output
    if (Kidx > 0) k_zero_rows<<<Kidx, DIM>>>(idx_wo, out);
    k_mlp1<<<(G + 7) / 8, HID>>>(Wp1, bp1, G);
    k_mlp2<<<(G + 7) / 8, DIM>>>(Wp2, bp2, idx_wo, Kidx, G, out);
}

// round 4
// speedup vs baseline: 1.8867x; 1.1839x over previous
#include <cuda_runtime.h>
#include <cuda_bf16.h>
#include <math.h>

// ---------------------------------------------------------------------------
// Drugemb: 2-layer GCN + WeightedSumAndMax readout + 2-layer MLP head.
// R4: persistent tensor-core dual-GEMM (weights loaded to smem ONCE per SM,
// loop over row tiles) -> kills ~525MB of redundant weight traffic.
// norm computation fused into scan kernels.
// ---------------------------------------------------------------------------

#define NODE_F 74
#define HID 128
#define DIM 256

#define N_MAX 131072
#define E_MAX 524288
#define G_MAX 8192
#define SCAN_TPB 1024

typedef unsigned int u32;
typedef __nv_bfloat16 bf16;

#define KP1 88
#define KP2 136
#define WSEG1 (128 * KP1)
#define WSEG2 (128 * KP2)

// ---- scratch ----
__device__ float g_norm_s[N_MAX];
__device__ float g_norm_d[N_MAX];
__device__ int   g_outdeg[N_MAX];
__device__ int   g_indeg[N_MAX];
__device__ int   g_fill[N_MAX];
__device__ int   g_rowptr[N_MAX + 1];
__device__ int   g_blksum[N_MAX / SCAN_TPB + 2];
__device__ int   g_csr_src[E_MAX];
__device__ float g_agg[(size_t)N_MAX * HID];
__device__ float g_h1[(size_t)N_MAX * HID];
__device__ float g_h2[(size_t)N_MAX * HID];
__device__ float g_aw[N_MAX];
__device__ int   g_gstart[G_MAX + 1];
__device__ float g_gfeat[(size_t)G_MAX * 2 * HID];
__device__ float g_hidden[(size_t)G_MAX * HID];
__device__ bf16  g_wt[4 * WSEG1 + 4 * WSEG2];

// ---------------------------------------------------------------------------
__global__ void k_zero3(int n) {
    int i = blockIdx.x * blockDim.x + threadIdx.x;
    if (i < n) { g_outdeg[i] = 0; g_indeg[i] = 0; g_fill[i] = 0; }
}

__global__ void k_zero_rows(const int* __restrict__ idx, float* __restrict__ o) {
    int r = idx[blockIdx.x];
    o[(size_t)r * DIM + threadIdx.x] = 0.0f;
}

__global__ void k_deg(const int* __restrict__ src, const int* __restrict__ dst, int E) {
    int e = blockIdx.x * blockDim.x + threadIdx.x;
    if (e < E) {
        atomicAdd(&g_outdeg[src[e]], 1);
        atomicAdd(&g_indeg[dst[e]], 1);
    }
}

// ---- weight conversion ----
__global__ void k_convw(const float* __restrict__ W, const float* __restrict__ Wr,
                        int K, int Kp, bf16* __restrict__ base) {
    int i = blockIdx.x * blockDim.x + threadIdx.x;
    int seg = 128 * Kp;
    if (i >= 2 * seg) return;
    const float* S = (i < seg) ? W : Wr;
    bf16* hi = (i < seg) ? base : base + 2 * seg;
    bf16* lo = hi + seg;
    int j = (i < seg) ? i : i - seg;
    int n = j / Kp, k = j - n * Kp;
    float v = (k < K) ? S[k * 128 + n] : 0.0f;
    bf16 h = __float2bfloat16_rn(v);
    bf16 l = __float2bfloat16_rn(v - __bfloat162float(h));
    hi[j] = h;
    lo[j] = l;
}

// ---- scan (+ fused norm computation) ----
__global__ void k_scan1(int n) {
    __shared__ int wsum[32];
    int tid = threadIdx.x, lane = tid & 31, warp = tid >> 5;
    int i = blockIdx.x * SCAN_TPB + tid;
    int v = (i < n) ? g_indeg[i] : 0;
    if (i < n) g_norm_d[i] = rsqrtf(fmaxf((float)v, 1.0f));
    int x = v;
    #pragma unroll
    for (int o = 1; o < 32; o <<= 1) {
        int t = __shfl_up_sync(0xffffffffu, x, o);
        if (lane >= o) x += t;
    }
    if (lane == 31) wsum[warp] = x;
    __syncthreads();
    if (warp == 0) {
        int s2 = wsum[lane];
        int y = s2;
        #pragma unroll
        for (int o = 1; o < 32; o <<= 1) {
            int t = __shfl_up_sync(0xffffffffu, y, o);
            if (lane >= o) y += t;
        }
        wsum[lane] = y - s2;
    }
    __syncthreads();
    int incl = x + wsum[warp];
    if (i < n) g_rowptr[i] = incl - v;
    if (tid == SCAN_TPB - 1) g_blksum[blockIdx.x] = incl;
}

__global__ void k_scan2(int nblk, int n, int e_total) {
    __shared__ int wsum[32];
    int tid = threadIdx.x, lane = tid & 31, warp = tid >> 5;
    int v = (tid < nblk) ? g_blksum[tid] : 0;
    int x = v;
    #pragma unroll
    for (int o = 1; o < 32; o <<= 1) {
        int t = __shfl_up_sync(0xffffffffu, x, o);
        if (lane >= o) x += t;
    }
    if (lane == 31) wsum[warp] = x;
    __syncthreads();
    if (warp == 0) {
        int s2 = wsum[lane];
        int y = s2;
        #pragma unroll
        for (int o = 1; o < 32; o <<= 1) {
            int t = __shfl_up_sync(0xffffffffu, y, o);
            if (lane >= o) y += t;
        }
        wsum[lane] = y - s2;
    }
    __syncthreads();
    if (tid < nblk) g_blksum[tid] = x + wsum[warp] - v;
    if (tid == 0) g_rowptr[n] = e_total;
}

__global__ void k_scan3(int n) {
    int i = blockIdx.x * SCAN_TPB + threadIdx.x;
    if (i < n) {
        g_rowptr[i] += g_blksum[blockIdx.x];
        g_norm_s[i] = rsqrtf(fmaxf((float)g_outdeg[i], 1.0f));
    }
}

__global__ void k_fill_csr(const int* __restrict__ src, const int* __restrict__ dst, int E) {
    int e = blockIdx.x * blockDim.x + threadIdx.x;
    if (e < E) {
        int d = dst[e];
        int pos = g_rowptr[d] + atomicAdd(&g_fill[d], 1);
        g_csr_src[pos] = src[e];
    }
}

// warp-per-node CSR aggregation, scalar (F=74)
__global__ void k_aggregate74(const float* __restrict__ hin, float* __restrict__ aggout, int n) {
    int w = (blockIdx.x * blockDim.x + threadIdx.x) >> 5;
    int lane = threadIdx.x & 31;
    if (w >= n) return;
    float a0 = 0.0f, a1 = 0.0f, a2 = 0.0f;
    int e0 = g_rowptr[w], e1 = g_rowptr[w + 1];
    for (int e = e0; e < e1; e++) {
        int s = g_csr_src[e];
        float ns = g_norm_s[s];
        const float* row = hin + (size_t)s * NODE_F;
        a0 += ns * __ldg(&row[lane]);
        a1 += ns * __ldg(&row[lane + 32]);
        if (lane < NODE_F - 64) a2 += ns * __ldg(&row[lane + 64]);
    }
    float nd = g_norm_d[w];
    float* orow = aggout + (size_t)w * NODE_F;
    orow[lane] = a0 * nd;
    orow[lane + 32] = a1 * nd;
    if (lane < NODE_F - 64) orow[lane + 64] = a2 * nd;
}

// warp-per-node CSR aggregation, float4 (F=128)
__global__ void k_aggregate128(const float* __restrict__ hin, float* __restrict__ aggout, int n) {
    int w = (blockIdx.x * blockDim.x + threadIdx.x) >> 5;
    int lane = threadIdx.x & 31;
    if (w >= n) return;
    float4 acc = make_float4(0.f, 0.f, 0.f, 0.f);
    int e0 = g_rowptr[w], e1 = g_rowptr[w + 1];
    for (int e = e0; e < e1; e++) {
        int s = g_csr_src[e];
        float ns = g_norm_s[s];
        float4 v = __ldg((const float4*)(hin + (size_t)s * HID) + lane);
        acc.x += ns * v.x; acc.y += ns * v.y; acc.z += ns * v.z; acc.w += ns * v.w;
    }
    float nd = g_norm_d[w];
    acc.x *= nd; acc.y *= nd; acc.z *= nd; acc.w *= nd;
    ((float4*)(aggout + (size_t)w * HID))[lane] = acc;
}

// ---- persistent tensor-core dual GEMM ----
__device__ __forceinline__ void mma16816(float* c, const u32* a, const u32* b) {
    asm volatile(
        "mma.sync.aligned.m16n8k16.row.col.f32.bf16.bf16.f32 "
        "{%0,%1,%2,%3}, {%4,%5,%6,%7}, {%8,%9}, {%0,%1,%2,%3};"
        : "+f"(c[0]), "+f"(c[1]), "+f"(c[2]), "+f"(c[3])
        : "r"(a[0]), "r"(a[1]), "r"(a[2]), "r"(a[3]), "r"(b[0]), "r"(b[1]));
}

// Out[N x 128] = relu(X@W + b) + relu(Y@Wr + br)
// Persistent: weights -> smem once, then loop tiles of 64 rows.
template <int K, int Kp, int Kceil>
__global__ void __launch_bounds__(256, 1)
k_mma_gemm(const float* __restrict__ X, const float* __restrict__ Y,
           const bf16* __restrict__ wbase,
           const float* __restrict__ b, const float* __restrict__ br,
           float* __restrict__ Out, int n, int ntiles) {
    extern __shared__ char sm_raw[];
    bf16* sW = (bf16*)sm_raw;            // 4*128*Kp
    bf16* sX = sW + 4 * 128 * Kp;        // 4*64*Kp
    int tid = threadIdx.x;

    // weights -> smem ONCE
    {
        const uint4* gsrc = (const uint4*)wbase;
        uint4* sdst = (uint4*)sW;
        const int n16 = 4 * 128 * Kp / 8;
        for (int i = tid; i < n16; i += 256) sdst[i] = gsrc[i];
    }

    bf16* sXhi = sX;
    bf16* sXlo = sX + 64 * Kp;
    bf16* sYhi = sX + 128 * Kp;
    bf16* sYlo = sX + 192 * Kp;

    // zero K-pad region once (constant across tiles)
    if (Kceil > K) {
        bf16 z = __float2bfloat16_rn(0.0f);
        for (int i = tid; i < 64 * (Kceil - K); i += 256) {
            int r = i / (Kceil - K), k = K + i % (Kceil - K);
            sXhi[r * Kp + k] = z; sXlo[r * Kp + k] = z;
            sYhi[r * Kp + k] = z; sYlo[r * Kp + k] = z;
        }
    }

    const u32* uS = (const u32*)sm_raw;
    const int KW = Kp / 2;
    const int W0 = 0;
    const int W1 = 64 * Kp;
    const int R0 = 128 * Kp;
    const int R1 = 192 * Kp;
    const int XH = 256 * Kp;
    const int XL = XH + 32 * Kp;
    const int YH = XH + 64 * Kp;
    const int YL = XH + 96 * Kp;

    int lane = tid & 31, warp = tid >> 5;
    int wm = warp >> 1;
    int wn = warp & 1;
    int g = lane >> 2, t = lane & 3;
    const int rowA = (wm * 16 + g) * KW;
    constexpr int KSTEPS = Kceil / 16;

    for (int tile = blockIdx.x; tile < ntiles; tile += gridDim.x) {
        int row0 = tile * 64;
        __syncthreads();  // previous iteration's readers done before overwrite

        // load + convert X/Y tile
        for (int i = tid; i < 64 * K; i += 256) {
            int r = i / K, k = i - r * K;
            int gr = row0 + r;
            float xv = 0.0f, yv = 0.0f;
            if (gr < n) {
                xv = __ldg(&X[(size_t)gr * K + k]);
                yv = __ldg(&Y[(size_t)gr * K + k]);
            }
            bf16 xh = __float2bfloat16_rn(xv);
            bf16 yh = __float2bfloat16_rn(yv);
            sXhi[r * Kp + k] = xh;
            sXlo[r * Kp + k] = __float2bfloat16_rn(xv - __bfloat162float(xh));
            sYhi[r * Kp + k] = yh;
            sYlo[r * Kp + k] = __float2bfloat16_rn(yv - __bfloat162float(yh));
        }
        __syncthreads();

        float acc1[8][4], acc2[8][4];
        #pragma unroll
        for (int j = 0; j < 8; j++)
            #pragma unroll
            for (int q = 0; q < 4; q++) { acc1[j][q] = 0.0f; acc2[j][q] = 0.0f; }

        #pragma unroll
        for (int kt = 0; kt < KSTEPS; kt++) {
            const int ko = kt * 8 + t;
            u32 xh[4], xl[4], yh[4], yl[4];
            xh[0] = uS[XH + rowA + ko];          xh[1] = uS[XH + rowA + 4 * Kp + ko];
            xh[2] = uS[XH + rowA + ko + 4];      xh[3] = uS[XH + rowA + 4 * Kp + ko + 4];
            xl[0] = uS[XL + rowA + ko];          xl[1] = uS[XL + rowA + 4 * Kp + ko];
            xl[2] = uS[XL + rowA + ko + 4];      xl[3] = uS[XL + rowA + 4 * Kp + ko + 4];
            yh[0] = uS[YH + rowA + ko];          yh[1] = uS[YH + rowA + 4 * Kp + ko];
            yh[2] = uS[YH + rowA + ko + 4];      yh[3] = uS[YH + rowA + 4 * Kp + ko + 4];
            yl[0] = uS[YL + rowA + ko];          yl[1] = uS[YL + rowA + 4 * Kp + ko];
            yl[2] = uS[YL + rowA + ko + 4];      yl[3] = uS[YL + rowA + 4 * Kp + ko + 4];

            #pragma unroll
            for (int j = 0; j < 8; j++) {
                const int colB = (wn * 64 + j * 8 + g) * KW + ko;
                u32 wh[2], wl[2], rh[2], rl[2];
                wh[0] = uS[W0 + colB]; wh[1] = uS[W0 + colB + 4];
                wl[0] = uS[W1 + colB]; wl[1] = uS[W1 + colB + 4];
                rh[0] = uS[R0 + colB]; rh[1] = uS[R0 + colB + 4];
                rl[0] = uS[R1 + colB]; rl[1] = uS[R1 + colB + 4];
                mma16816(acc1[j], xh, wh);
                mma16816(acc1[j], xh, wl);
                mma16816(acc1[j], xl, wh);
                mma16816(acc2[j], yh, rh);
                mma16816(acc2[j], yh, rl);
                mma16816(acc2[j], yl, rh);
            }
        }

        int r0 = row0 + wm * 16 + g;
        int r1 = r0 + 8;
        #pragma unroll
        for (int j = 0; j < 8; j++) {
            int c = wn * 64 + j * 8 + 2 * t;
            float b0 = __ldg(&b[c]), b1v = __ldg(&b[c + 1]);
            float q0 = __ldg(&br[c]), q1 = __ldg(&br[c + 1]);
            if (r0 < n) {
                float2 v;
                v.x = fmaxf(acc1[j][0] + b0, 0.0f) + fmaxf(acc2[j][0] + q0, 0.0f);
                v.y = fmaxf(acc1[j][1] + b1v, 0.0f) + fmaxf(acc2[j][1] + q1, 0.0f);
                *(float2*)(Out + (size_t)r0 * 128 + c) = v;
            }
            if (r1 < n) {
                float2 v;
                v.x = fmaxf(acc1[j][2] + b0, 0.0f) + fmaxf(acc2[j][2] + q0, 0.0f);
                v.y = fmaxf(acc1[j][3] + b1v, 0.0f) + fmaxf(acc2[j][3] + q1, 0.0f);
                *(float2*)(Out + (size_t)r1 * 128 + c) = v;
            }
        }
    }
}

// aw[i] = sigmoid(h2[i] . w_atom + b_atom); warp per node
__global__ void k_aw(const float* __restrict__ wa, const float* __restrict__ ba, int n) {
    int w = (blockIdx.x * blockDim.x + threadIdx.x) >> 5;
    int lane = threadIdx.x & 31;
    if (w >= n) return;
    const float* row = g_h2 + (size_t)w * HID;
    float d = 0.0f;
    #pragma unroll
    for (int j = 0; j < 4; j++) d += row[lane + 32 * j] * __ldg(&wa[lane + 32 * j]);
    #pragma unroll
    for (int o = 16; o > 0; o >>= 1) d += __shfl_xor_sync(0xffffffffu, d, o);
    if (lane == 0) g_aw[w] = 1.0f / (1.0f + expf(-(d + ba[0])));
}

__global__ void k_gbound(const int* __restrict__ gid, int n, int G) {
    int i = blockIdx.x * blockDim.x + threadIdx.x;
    if (i < n) {
        int g = gid[i];
        if (i == 0 || gid[i - 1] != g) g_gstart[g] = i;
        if (i == n - 1) g_gstart[G] = n;
    }
}

// block per graph, thread per feature: weighted sum + max
__global__ void k_readout(int G) {
    int g = blockIdx.x;
    int f = threadIdx.x;
    if (g >= G) return;
    int s = g_gstart[g], e = g_gstart[g + 1];
    float sum = 0.0f, mx = -3.4e38f;
    for (int i = s; i < e; i++) {
        float v = g_h2[(size_t)i * HID + f];
        sum += g_aw[i] * v;
        mx = fmaxf(mx, v);
    }
    g_gfeat[(size_t)g * 2 * HID + f] = sum;
    g_gfeat[(size_t)g * 2 * HID + HID + f] = mx;
}

__global__ void k_mlp1(const float* __restrict__ Wp1, const float* __restrict__ bp1, int G) {
    int g0 = blockIdx.x * 8;
    int tid = threadIdx.x;
    float acc[8];
    #pragma unroll
    for (int j = 0; j < 8; j++) acc[j] = 0.0f;
    for (int k = 0; k < 2 * HID; k++) {
        float w = __ldg(&Wp1[k * HID + tid]);
        #pragma unroll
        for (int j = 0; j < 8; j++) {
            int g = g0 + j;
            if (g < G) acc[j] += g_gfeat[(size_t)g * 2 * HID + k] * w;
        }
    }
    float bb = __ldg(&bp1[tid]);
    #pragma unroll
    for (int j = 0; j < 8; j++) {
        int g = g0 + j;
        if (g < G) g_hidden[(size_t)g * HID + tid] = fmaxf(acc[j] + bb, 0.0f);
    }
}

__global__ void k_mlp2(const float* __restrict__ Wp2, const float* __restrict__ bp2,
                       const int* __restrict__ idx, int Kidx, int G,
                       float* __restrict__ out) {
    int g0 = blockIdx.x * 8;
    int tid = threadIdx.x;
    float acc[8];
    #pragma unroll
    for (int j = 0; j < 8; j++) acc[j] = 0.0f;
    for (int k = 0; k < HID; k++) {
        float w = __ldg(&Wp2[k * DIM + tid]);
        #pragma unroll
        for (int j = 0; j < 8; j++) {
            int g = g0 + j;
            if (g < G) acc[j] += g_hidden[(size_t)g * HID + k] * w;
        }
    }
    float bb = __ldg(&bp2[tid]);
    #pragma unroll
    for (int j = 0; j < 8; j++) {
        int g = g0 + j;
        if (g < G) {
            int p = g;
            for (int t = 0; t < Kidx; t++) {
                if (__ldg(&idx[t]) <= p) p++;
            }
            out[(size_t)p * DIM + tid] = acc[j] + bb;
        }
    }
}

// ---------------------------------------------------------------------------
extern "C" void kernel_launch(void* const* d_in, const int* in_sizes, int n_in,
                              void* d_out, int out_size) {
    const float* node_feats = (const float*)d_in[0];
    const float* W1  = (const float*)d_in[2];
    const float* b1  = (const float*)d_in[3];
    const float* Wr1 = (const float*)d_in[4];
    const float* br1 = (const float*)d_in[5];
    const float* W2  = (const float*)d_in[6];
    const float* b2  = (const float*)d_in[7];
    const float* Wr2 = (const float*)d_in[8];
    const float* br2 = (const float*)d_in[9];
    const float* w_atom = (const float*)d_in[10];
    const float* b_atom = (const float*)d_in[11];
    const float* Wp1 = (const float*)d_in[12];
    const float* bp1 = (const float*)d_in[13];
    const float* Wp2 = (const float*)d_in[14];
    const float* bp2 = (const float*)d_in[15];
    const int* src = (const int*)d_in[16];
    const int* dst = (const int*)d_in[17];
    const int* graph_ids = (const int*)d_in[18];
    const int* idx_wo = (const int*)d_in[19];
    float* out = (float*)d_out;

    int N = in_sizes[0] / NODE_F;
    int E = in_sizes[16];
    int Kidx = in_sizes[19];
    int total = out_size / DIM;
    int G = total - Kidx;

    float *p_agg, *p_h1, *p_h2;
    bf16 *p_wt;
    cudaGetSymbolAddress((void**)&p_agg, g_agg);
    cudaGetSymbolAddress((void**)&p_h1, g_h1);
    cudaGetSymbolAddress((void**)&p_h2, g_h2);
    cudaGetSymbolAddress((void**)&p_wt, g_wt);

    const int SMEM1 = (4 * 128 * KP1 + 4 * 64 * KP1) * 2;
    const int SMEM2 = (4 * 128 * KP2 + 4 * 64 * KP2) * 2;
    cudaFuncSetAttribute(k_mma_gemm<74, KP1, 80>, cudaFuncAttributeMaxDynamicSharedMemorySize, SMEM1);
    cudaFuncSetAttribute(k_mma_gemm<128, KP2, 128>, cudaFuncAttributeMaxDynamicSharedMemorySize, SMEM2);

    int tb = 256;
    int gN = (N + tb - 1) / tb;
    int gE = (E + tb - 1) / tb;
    int gW = (N + 7) / 8;
    int nScanBlk = (N + SCAN_TPB - 1) / SCAN_TPB;
    int ntiles = (N + 63) / 64;
    int gGemm = (ntiles < 148) ? ntiles : 148;

    // 0. weight conversion
    k_convw<<<(2 * 128 * KP1 + tb - 1) / tb, tb>>>(W1, Wr1, 74, KP1, p_wt);
    k_convw<<<(2 * 128 * KP2 + tb - 1) / tb, tb>>>(W2, Wr2, 128, KP2, p_wt + 4 * WSEG1);

    // 1. degrees + norms + CSR
    k_zero3<<<gN, tb>>>(N);
    k_deg<<<gE, tb>>>(src, dst, E);
    k_scan1<<<nScanBlk, SCAN_TPB>>>(N);
    k_scan2<<<1, 1024>>>(nScanBlk, N, E);
    k_scan3<<<nScanBlk, SCAN_TPB>>>(N);
    k_fill_csr<<<gE, tb>>>(src, dst, E);

    // 2. layer 1
    k_aggregate74<<<gW, tb>>>(node_feats, p_agg, N);
    k_mma_gemm<74, KP1, 80><<<gGemm, 256, SMEM1>>>(p_agg, node_feats, p_wt, b1, br1, p_h1, N, ntiles);

    // 3. layer 2
    k_aggregate128<<<gW, tb>>>(p_h1, p_agg, N);
    k_mma_gemm<128, KP2, 128><<<gGemm, 256, SMEM2>>>(p_agg, p_h1, p_wt + 4 * WSEG1, b2, br2, p_h2, N, ntiles);

    // 4. readout
    k_aw<<<gW, tb>>>(w_atom, b_atom, N);
    k_gbound<<<gN, tb>>>(graph_ids, N, G);
    k_readout<<<G, HID>>>(G);

    // 5. MLP head + output
    if (Kidx > 0) k_zero_rows<<<Kidx, DIM>>>(idx_wo, out);
    k_mlp1<<<(G + 7) / 8, HID>>>(Wp1, bp1, G);
    k_mlp2<<<(G + 7) / 8, DIM>>>(Wp2, bp2, idx_wo, Kidx, G, out);
}

// round 5
// speedup vs baseline: 1.9524x; 1.0348x over previous
#include <cuda_runtime.h>
#include <cuda_bf16.h>
#include <math.h>

// ---------------------------------------------------------------------------
// Drugemb R5: bf16 hi/lo planes as interchange format.
// Producers (aggregation, conversions, GEMM1 epilogue) emit split-bf16 planes;
// GEMM tile loads are pure uint4 copies. fp32 h1 eliminated. k_aw fused into
// GEMM2 epilogue (quad-reduced atomics). Persistent tensor-core dual-GEMMs.
// ---------------------------------------------------------------------------

#define NODE_F 74
#define HID 128
#define DIM 256

#define N_MAX 131072
#define E_MAX 524288
#define G_MAX 8192
#define SCAN_TPB 1024

typedef unsigned int u32;
typedef __nv_bfloat16 bf16;

#define KC1 80      // layer1 logical K padded to 80 (cols 74..79 zero)
#define KC2 128
#define KP1 88      // smem strides
#define KP2 136
#define WSEG1 (128 * KP1)
#define WSEG2 (128 * KP2)

// ---- scratch ----
__device__ float g_norm_s[N_MAX];
__device__ float g_norm_d[N_MAX];
__device__ int   g_outdeg[N_MAX];
__device__ int   g_indeg[N_MAX];
__device__ int   g_fill[N_MAX];
__device__ int   g_rowptr[N_MAX + 1];
__device__ int   g_blksum[N_MAX / SCAN_TPB + 2];
__device__ int   g_csr_src[E_MAX];
__device__ bf16  g_y1hi[(size_t)N_MAX * KC1];
__device__ bf16  g_y1lo[(size_t)N_MAX * KC1];
__device__ bf16  g_x1hi[(size_t)N_MAX * KC1];
__device__ bf16  g_x1lo[(size_t)N_MAX * KC1];
__device__ bf16  g_h1hi[(size_t)N_MAX * HID];
__device__ bf16  g_h1lo[(size_t)N_MAX * HID];
__device__ bf16  g_x2hi[(size_t)N_MAX * HID];
__device__ bf16  g_x2lo[(size_t)N_MAX * HID];
__device__ float g_h2[(size_t)N_MAX * HID];
__device__ float g_awraw[N_MAX];
__device__ float g_aw[N_MAX];
__device__ int   g_gstart[G_MAX + 1];
__device__ float g_gfeat[(size_t)G_MAX * 2 * HID];
__device__ float g_hidden[(size_t)G_MAX * HID];
__device__ bf16  g_wt[4 * WSEG1 + 4 * WSEG2];

__device__ __forceinline__ void split_bf16(float v, bf16& h, bf16& l) {
    h = __float2bfloat16_rn(v);
    l = __float2bfloat16_rn(v - __bfloat162float(h));
}

// ---------------------------------------------------------------------------
__global__ void k_zero3(int n) {
    int i = blockIdx.x * blockDim.x + threadIdx.x;
    if (i < n) { g_outdeg[i] = 0; g_indeg[i] = 0; g_fill[i] = 0; g_awraw[i] = 0.0f; }
}

__global__ void k_zero_rows(const int* __restrict__ idx, float* __restrict__ o) {
    int r = idx[blockIdx.x];
    o[(size_t)r * DIM + threadIdx.x] = 0.0f;
}

__global__ void k_deg(const int* __restrict__ src, const int* __restrict__ dst, int E) {
    int e = blockIdx.x * blockDim.x + threadIdx.x;
    if (e < E) {
        atomicAdd(&g_outdeg[src[e]], 1);
        atomicAdd(&g_indeg[dst[e]], 1);
    }
}

// ---- weight conversion (transposed, padded, split) ----
__global__ void k_convw(const float* __restrict__ W, const float* __restrict__ Wr,
                        int K, int Kp, bf16* __restrict__ base) {
    int i = blockIdx.x * blockDim.x + threadIdx.x;
    int seg = 128 * Kp;
    if (i >= 2 * seg) return;
    const float* S = (i < seg) ? W : Wr;
    bf16* hi = (i < seg) ? base : base + 2 * seg;
    bf16* lo = hi + seg;
    int j = (i < seg) ? i : i - seg;
    int n = j / Kp, k = j - n * Kp;
    float v = (k < K) ? S[k * 128 + n] : 0.0f;
    bf16 h, l; split_bf16(v, h, l);
    hi[j] = h; lo[j] = l;
}

// node_feats fp32 [N x 74] -> Y1 planes [N x 80] bf16 hi/lo (pair per thread)
__global__ void k_convY1(const float* __restrict__ nf, int n) {
    int i = blockIdx.x * blockDim.x + threadIdx.x;
    if (i >= n * (KC1 / 2)) return;
    int row = i / (KC1 / 2);
    int col = (i - row * (KC1 / 2)) * 2;
    float v0 = 0.0f, v1 = 0.0f;
    if (col < NODE_F - 1) {
        float2 t = *(const float2*)(nf + (size_t)row * NODE_F + col);
        v0 = t.x; v1 = t.y;
    }
    bf16 h0, l0, h1, l1;
    split_bf16(v0, h0, l0);
    split_bf16(v1, h1, l1);
    size_t o = (size_t)row * KC1 + col;
    *(__nv_bfloat162*)(g_y1hi + o) = __nv_bfloat162(h0, h1);
    *(__nv_bfloat162*)(g_y1lo + o) = __nv_bfloat162(l0, l1);
}

// ---- scan (+ fused norm computation) ----
__global__ void k_scan1(int n) {
    __shared__ int wsum[32];
    int tid = threadIdx.x, lane = tid & 31, warp = tid >> 5;
    int i = blockIdx.x * SCAN_TPB + tid;
    int v = (i < n) ? g_indeg[i] : 0;
    if (i < n) g_norm_d[i] = rsqrtf(fmaxf((float)v, 1.0f));
    int x = v;
    #pragma unroll
    for (int o = 1; o < 32; o <<= 1) {
        int t = __shfl_up_sync(0xffffffffu, x, o);
        if (lane >= o) x += t;
    }
    if (lane == 31) wsum[warp] = x;
    __syncthreads();
    if (warp == 0) {
        int s2 = wsum[lane];
        int y = s2;
        #pragma unroll
        for (int o = 1; o < 32; o <<= 1) {
            int t = __shfl_up_sync(0xffffffffu, y, o);
            if (lane >= o) y += t;
        }
        wsum[lane] = y - s2;
    }
    __syncthreads();
    int incl = x + wsum[warp];
    if (i < n) g_rowptr[i] = incl - v;
    if (tid == SCAN_TPB - 1) g_blksum[blockIdx.x] = incl;
}

__global__ void k_scan2(int nblk, int n, int e_total) {
    __shared__ int wsum[32];
    int tid = threadIdx.x, lane = tid & 31, warp = tid >> 5;
    int v = (tid < nblk) ? g_blksum[tid] : 0;
    int x = v;
    #pragma unroll
    for (int o = 1; o < 32; o <<= 1) {
        int t = __shfl_up_sync(0xffffffffu, x, o);
        if (lane >= o) x += t;
    }
    if (lane == 31) wsum[warp] = x;
    __syncthreads();
    if (warp == 0) {
        int s2 = wsum[lane];
        int y = s2;
        #pragma unroll
        for (int o = 1; o < 32; o <<= 1) {
            int t = __shfl_up_sync(0xffffffffu, y, o);
            if (lane >= o) y += t;
        }
        wsum[lane] = y - s2;
    }
    __syncthreads();
    if (tid < nblk) g_blksum[tid] = x + wsum[warp] - v;
    if (tid == 0) g_rowptr[n] = e_total;
}

__global__ void k_scan3(int n) {
    int i = blockIdx.x * SCAN_TPB + threadIdx.x;
    if (i < n) {
        g_rowptr[i] += g_blksum[blockIdx.x];
        g_norm_s[i] = rsqrtf(fmaxf((float)g_outdeg[i], 1.0f));
    }
}

__global__ void k_fill_csr(const int* __restrict__ src, const int* __restrict__ dst, int E) {
    int e = blockIdx.x * blockDim.x + threadIdx.x;
    if (e < E) {
        int d = dst[e];
        int pos = g_rowptr[d] + atomicAdd(&g_fill[d], 1);
        g_csr_src[pos] = src[e];
    }
}

// warp-per-node aggregation of node_feats (fp32 gather) -> X1 planes
__global__ void k_aggregate74(const float* __restrict__ hin, int n) {
    int w = (blockIdx.x * blockDim.x + threadIdx.x) >> 5;
    int lane = threadIdx.x & 31;
    if (w >= n) return;
    float a0 = 0.0f, a1 = 0.0f, a2 = 0.0f;
    int e0 = g_rowptr[w], e1 = g_rowptr[w + 1];
    for (int e = e0; e < e1; e++) {
        int s = g_csr_src[e];
        float ns = g_norm_s[s];
        const float* row = hin + (size_t)s * NODE_F;
        a0 += ns * __ldg(&row[lane]);
        a1 += ns * __ldg(&row[lane + 32]);
        if (lane < NODE_F - 64) a2 += ns * __ldg(&row[lane + 64]);
    }
    float nd = g_norm_d[w];
    size_t o = (size_t)w * KC1;
    bf16 h, l;
    split_bf16(a0 * nd, h, l);
    g_x1hi[o + lane] = h; g_x1lo[o + lane] = l;
    split_bf16(a1 * nd, h, l);
    g_x1hi[o + lane + 32] = h; g_x1lo[o + lane + 32] = l;
    if (lane < 16) {
        float v2 = (lane < NODE_F - 64) ? a2 * nd : 0.0f;
        split_bf16(v2, h, l);
        g_x1hi[o + lane + 64] = h; g_x1lo[o + lane + 64] = l;
    }
}

// warp-per-node aggregation of H1 planes -> X2 planes
__global__ void k_aggregate128(int n) {
    int w = (blockIdx.x * blockDim.x + threadIdx.x) >> 5;
    int lane = threadIdx.x & 31;
    if (w >= n) return;
    float acc0 = 0.f, acc1 = 0.f, acc2 = 0.f, acc3 = 0.f;
    int e0 = g_rowptr[w], e1 = g_rowptr[w + 1];
    for (int e = e0; e < e1; e++) {
        int s = g_csr_src[e];
        float ns = g_norm_s[s];
        size_t o = (size_t)s * HID + lane * 4;
        __nv_bfloat162 h01 = *(const __nv_bfloat162*)(g_h1hi + o);
        __nv_bfloat162 h23 = *(const __nv_bfloat162*)(g_h1hi + o + 2);
        __nv_bfloat162 l01 = *(const __nv_bfloat162*)(g_h1lo + o);
        __nv_bfloat162 l23 = *(const __nv_bfloat162*)(g_h1lo + o + 2);
        float2 fh01 = __bfloat1622float2(h01), fh23 = __bfloat1622float2(h23);
        float2 fl01 = __bfloat1622float2(l01), fl23 = __bfloat1622float2(l23);
        acc0 += ns * (fh01.x + fl01.x);
        acc1 += ns * (fh01.y + fl01.y);
        acc2 += ns * (fh23.x + fl23.x);
        acc3 += ns * (fh23.y + fl23.y);
    }
    float nd = g_norm_d[w];
    bf16 h0, l0, h1, l1, h2, l2, h3, l3;
    split_bf16(acc0 * nd, h0, l0);
    split_bf16(acc1 * nd, h1, l1);
    split_bf16(acc2 * nd, h2, l2);
    split_bf16(acc3 * nd, h3, l3);
    size_t o = (size_t)w * HID + lane * 4;
    *(__nv_bfloat162*)(g_x2hi + o) = __nv_bfloat162(h0, h1);
    *(__nv_bfloat162*)(g_x2hi + o + 2) = __nv_bfloat162(h2, h3);
    *(__nv_bfloat162*)(g_x2lo + o) = __nv_bfloat162(l0, l1);
    *(__nv_bfloat162*)(g_x2lo + o + 2) = __nv_bfloat162(l2, l3);
}

// ---- persistent tensor-core dual GEMM ----
__device__ __forceinline__ void mma16816(float* c, const u32* a, const u32* b) {
    asm volatile(
        "mma.sync.aligned.m16n8k16.row.col.f32.bf16.bf16.f32 "
        "{%0,%1,%2,%3}, {%4,%5,%6,%7}, {%8,%9}, {%0,%1,%2,%3};"
        : "+f"(c[0]), "+f"(c[1]), "+f"(c[2]), "+f"(c[3])
        : "r"(a[0]), "r"(a[1]), "r"(a[2]), "r"(a[3]), "r"(b[0]), "r"(b[1]));
}

// MODE 0: write bf16 hi/lo planes (layer1 -> h1 planes)
// MODE 1: write fp32 + fused w_atom dot (layer2 -> h2, awraw)
template <int KC, int Kp, int MODE>
__global__ void __launch_bounds__(256, 1)
k_mma_gemm(const bf16* __restrict__ Xhi, const bf16* __restrict__ Xlo,
           const bf16* __restrict__ Yhi, const bf16* __restrict__ Ylo,
           const bf16* __restrict__ wbase,
           const float* __restrict__ b, const float* __restrict__ br,
           float* __restrict__ OutF, bf16* __restrict__ OutHi, bf16* __restrict__ OutLo,
           float* __restrict__ awraw, const float* __restrict__ w_atom,
           int n, int ntiles) {
    extern __shared__ char sm_raw[];
    bf16* sW = (bf16*)sm_raw;
    bf16* sX = sW + 4 * 128 * Kp;
    int tid = threadIdx.x;

    // weights -> smem once
    {
        const uint4* gsrc = (const uint4*)wbase;
        uint4* sdst = (uint4*)sW;
        const int n16 = 4 * 128 * Kp / 8;
        for (int i = tid; i < n16; i += 256) sdst[i] = gsrc[i];
    }

    bf16* sXhi = sX;
    bf16* sXlo = sX + 64 * Kp;
    bf16* sYhi = sX + 128 * Kp;
    bf16* sYlo = sX + 192 * Kp;

    const u32* uS = (const u32*)sm_raw;
    const int KW = Kp / 2;
    const int W0 = 0;
    const int W1 = 64 * Kp;
    const int R0 = 128 * Kp;
    const int R1 = 192 * Kp;
    const int XH = 256 * Kp;
    const int XL = XH + 32 * Kp;
    const int YH = XH + 64 * Kp;
    const int YL = XH + 96 * Kp;

    int lane = tid & 31, warp = tid >> 5;
    int wm = warp >> 1;
    int wn = warp & 1;
    int g = lane >> 2, t = lane & 3;
    const int rowA = (wm * 16 + g) * KW;
    constexpr int KSTEPS = KC / 16;
    constexpr int CPR = KC / 8;   // uint4 chunks per row

    // hoist tile-invariant epilogue constants
    float bj0[8], bj1[8], qj0[8], qj1[8], wa0[8], wa1[8];
    #pragma unroll
    for (int j = 0; j < 8; j++) {
        int c = wn * 64 + j * 8 + 2 * t;
        bj0[j] = __ldg(&b[c]);  bj1[j] = __ldg(&b[c + 1]);
        qj0[j] = __ldg(&br[c]); qj1[j] = __ldg(&br[c + 1]);
        if (MODE == 1) { wa0[j] = __ldg(&w_atom[c]); wa1[j] = __ldg(&w_atom[c + 1]); }
    }

    for (int tile = blockIdx.x; tile < ntiles; tile += gridDim.x) {
        int row0 = tile * 64;
        __syncthreads();

        // tile copy: 4 planes, pure uint4
        for (int i = tid; i < 64 * CPR; i += 256) {
            int r = i / CPR, cc = i - r * CPR;
            int gr = row0 + r;
            uint4 xh = {0,0,0,0}, xl = {0,0,0,0}, yh = {0,0,0,0}, yl = {0,0,0,0};
            if (gr < n) {
                size_t off = (size_t)gr * KC + cc * 8;
                xh = *(const uint4*)(Xhi + off);
                xl = *(const uint4*)(Xlo + off);
                yh = *(const uint4*)(Yhi + off);
                yl = *(const uint4*)(Ylo + off);
            }
            int so = r * Kp + cc * 8;
            *(uint4*)(sXhi + so) = xh;
            *(uint4*)(sXlo + so) = xl;
            *(uint4*)(sYhi + so) = yh;
            *(uint4*)(sYlo + so) = yl;
        }
        __syncthreads();

        float acc1[8][4], acc2[8][4];
        #pragma unroll
        for (int j = 0; j < 8; j++)
            #pragma unroll
            for (int q = 0; q < 4; q++) { acc1[j][q] = 0.0f; acc2[j][q] = 0.0f; }

        #pragma unroll
        for (int kt = 0; kt < KSTEPS; kt++) {
            const int ko = kt * 8 + t;
            u32 xh[4], xl[4], yh[4], yl[4];
            xh[0] = uS[XH + rowA + ko];          xh[1] = uS[XH + rowA + 4 * Kp + ko];
            xh[2] = uS[XH + rowA + ko + 4];      xh[3] = uS[XH + rowA + 4 * Kp + ko + 4];
            xl[0] = uS[XL + rowA + ko];          xl[1] = uS[XL + rowA + 4 * Kp + ko];
            xl[2] = uS[XL + rowA + ko + 4];      xl[3] = uS[XL + rowA + 4 * Kp + ko + 4];
            yh[0] = uS[YH + rowA + ko];          yh[1] = uS[YH + rowA + 4 * Kp + ko];
            yh[2] = uS[YH + rowA + ko + 4];      yh[3] = uS[YH + rowA + 4 * Kp + ko + 4];
            yl[0] = uS[YL + rowA + ko];          yl[1] = uS[YL + rowA + 4 * Kp + ko];
            yl[2] = uS[YL + rowA + ko + 4];      yl[3] = uS[YL + rowA + 4 * Kp + ko + 4];

            #pragma unroll
            for (int j = 0; j < 8; j++) {
                const int colB = (wn * 64 + j * 8 + g) * KW + ko;
                u32 wh[2], wl[2], rh[2], rl[2];
                wh[0] = uS[W0 + colB]; wh[1] = uS[W0 + colB + 4];
                wl[0] = uS[W1 + colB]; wl[1] = uS[W1 + colB + 4];
                rh[0] = uS[R0 + colB]; rh[1] = uS[R0 + colB + 4];
                rl[0] = uS[R1 + colB]; rl[1] = uS[R1 + colB + 4];
                mma16816(acc1[j], xh, wh);
                mma16816(acc1[j], xh, wl);
                mma16816(acc1[j], xl, wh);
                mma16816(acc2[j], yh, rh);
                mma16816(acc2[j], yh, rl);
                mma16816(acc2[j], yl, rh);
            }
        }

        int r0 = row0 + wm * 16 + g;
        int r1 = r0 + 8;
        float s0 = 0.0f, s1 = 0.0f;
        #pragma unroll
        for (int j = 0; j < 8; j++) {
            int c = wn * 64 + j * 8 + 2 * t;
            float v00 = fmaxf(acc1[j][0] + bj0[j], 0.0f) + fmaxf(acc2[j][0] + qj0[j], 0.0f);
            float v01 = fmaxf(acc1[j][1] + bj1[j], 0.0f) + fmaxf(acc2[j][1] + qj1[j], 0.0f);
            float v10 = fmaxf(acc1[j][2] + bj0[j], 0.0f) + fmaxf(acc2[j][2] + qj0[j], 0.0f);
            float v11 = fmaxf(acc1[j][3] + bj1[j], 0.0f) + fmaxf(acc2[j][3] + qj1[j], 0.0f);
            if (MODE == 0) {
                if (r0 < n) {
                    bf16 h0, l0, h1, l1;
                    split_bf16(v00, h0, l0); split_bf16(v01, h1, l1);
                    size_t o = (size_t)r0 * HID + c;
                    *(__nv_bfloat162*)(OutHi + o) = __nv_bfloat162(h0, h1);
                    *(__nv_bfloat162*)(OutLo + o) = __nv_bfloat162(l0, l1);
                }
                if (r1 < n) {
                    bf16 h0, l0, h1, l1;
                    split_bf16(v10, h0, l0); split_bf16(v11, h1, l1);
                    size_t o = (size_t)r1 * HID + c;
                    *(__nv_bfloat162*)(OutHi + o) = __nv_bfloat162(h0, h1);
                    *(__nv_bfloat162*)(OutLo + o) = __nv_bfloat162(l0, l1);
                }
            } else {
                if (r0 < n) *(float2*)(OutF + (size_t)r0 * HID + c) = make_float2(v00, v01);
                if (r1 < n) *(float2*)(OutF + (size_t)r1 * HID + c) = make_float2(v10, v11);
                s0 += v00 * wa0[j] + v01 * wa1[j];
                s1 += v10 * wa0[j] + v11 * wa1[j];
            }
        }
        if (MODE == 1) {
            // quad-reduce (lanes g*4 + t, t=0..3 share rows r0/r1)
            s0 += __shfl_xor_sync(0xffffffffu, s0, 1);
            s0 += __shfl_xor_sync(0xffffffffu, s0, 2);
            s1 += __shfl_xor_sync(0xffffffffu, s1, 1);
            s1 += __shfl_xor_sync(0xffffffffu, s1, 2);
            if (t == 0) {
                if (r0 < n) atomicAdd(&awraw[r0], s0);
                if (r1 < n) atomicAdd(&awraw[r1], s1);
            }
        }
    }
}

// finalize attention weights: sigmoid(awraw + b_atom)
__global__ void k_awfin(const float* __restrict__ ba, int n) {
    int i = blockIdx.x * blockDim.x + threadIdx.x;
    if (i < n) g_aw[i] = 1.0f / (1.0f + expf(-(g_awraw[i] + ba[0])));
}

__global__ void k_gbound(const int* __restrict__ gid, int n, int G) {
    int i = blockIdx.x * blockDim.x + threadIdx.x;
    if (i < n) {
        int g = gid[i];
        if (i == 0 || gid[i - 1] != g) g_gstart[g] = i;
        if (i == n - 1) g_gstart[G] = n;
    }
}

// block per graph, thread per feature: weighted sum + max
__global__ void k_readout(int G) {
    int g = blockIdx.x;
    int f = threadIdx.x;
    if (g >= G) return;
    int s = g_gstart[g], e = g_gstart[g + 1];
    float sum = 0.0f, mx = -3.4e38f;
    for (int i = s; i < e; i++) {
        float v = g_h2[(size_t)i * HID + f];
        sum += g_aw[i] * v;
        mx = fmaxf(mx, v);
    }
    g_gfeat[(size_t)g * 2 * HID + f] = sum;
    g_gfeat[(size_t)g * 2 * HID + HID + f] = mx;
}

__global__ void k_mlp1(const float* __restrict__ Wp1, const float* __restrict__ bp1, int G) {
    int g0 = blockIdx.x * 8;
    int tid = threadIdx.x;
    float acc[8];
    #pragma unroll
    for (int j = 0; j < 8; j++) acc[j] = 0.0f;
    for (int k = 0; k < 2 * HID; k++) {
        float w = __ldg(&Wp1[k * HID + tid]);
        #pragma unroll
        for (int j = 0; j < 8; j++) {
            int g = g0 + j;
            if (g < G) acc[j] += g_gfeat[(size_t)g * 2 * HID + k] * w;
        }
    }
    float bb = __ldg(&bp1[tid]);
    #pragma unroll
    for (int j = 0; j < 8; j++) {
        int g = g0 + j;
        if (g < G) g_hidden[(size_t)g * HID + tid] = fmaxf(acc[j] + bb, 0.0f);
    }
}

__global__ void k_mlp2(const float* __restrict__ Wp2, const float* __restrict__ bp2,
                       const int* __restrict__ idx, int Kidx, int G,
                       float* __restrict__ out) {
    int g0 = blockIdx.x * 8;
    int tid = threadIdx.x;
    float acc[8];
    #pragma unroll
    for (int j = 0; j < 8; j++) acc[j] = 0.0f;
    for (int k = 0; k < HID; k++) {
        float w = __ldg(&Wp2[k * DIM + tid]);
        #pragma unroll
        for (int j = 0; j < 8; j++) {
            int g = g0 + j;
            if (g < G) acc[j] += g_hidden[(size_t)g * HID + k] * w;
        }
    }
    float bb = __ldg(&bp2[tid]);
    #pragma unroll
    for (int j = 0; j < 8; j++) {
        int g = g0 + j;
        if (g < G) {
            int p = g;
            for (int t = 0; t < Kidx; t++) {
                if (__ldg(&idx[t]) <= p) p++;
            }
            out[(size_t)p * DIM + tid] = acc[j] + bb;
        }
    }
}

// ---------------------------------------------------------------------------
extern "C" void kernel_launch(void* const* d_in, const int* in_sizes, int n_in,
                              void* d_out, int out_size) {
    const float* node_feats = (const float*)d_in[0];
    const float* W1  = (const float*)d_in[2];
    const float* b1  = (const float*)d_in[3];
    const float* Wr1 = (const float*)d_in[4];
    const float* br1 = (const float*)d_in[5];
    const float* W2  = (const float*)d_in[6];
    const float* b2  = (const float*)d_in[7];
    const float* Wr2 = (const float*)d_in[8];
    const float* br2 = (const float*)d_in[9];
    const float* w_atom = (const float*)d_in[10];
    const float* b_atom = (const float*)d_in[11];
    const float* Wp1 = (const float*)d_in[12];
    const float* bp1 = (const float*)d_in[13];
    const float* Wp2 = (const float*)d_in[14];
    const float* bp2 = (const float*)d_in[15];
    const int* src = (const int*)d_in[16];
    const int* dst = (const int*)d_in[17];
    const int* graph_ids = (const int*)d_in[18];
    const int* idx_wo = (const int*)d_in[19];
    float* out = (float*)d_out;

    int N = in_sizes[0] / NODE_F;
    int E = in_sizes[16];
    int Kidx = in_sizes[19];
    int total = out_size / DIM;
    int G = total - Kidx;

    bf16 *p_wt, *p_y1hi, *p_y1lo, *p_x1hi, *p_x1lo;
    bf16 *p_h1hi, *p_h1lo, *p_x2hi, *p_x2lo;
    float *p_h2, *p_awraw;
    cudaGetSymbolAddress((void**)&p_wt, g_wt);
    cudaGetSymbolAddress((void**)&p_y1hi, g_y1hi);
    cudaGetSymbolAddress((void**)&p_y1lo, g_y1lo);
    cudaGetSymbolAddress((void**)&p_x1hi, g_x1hi);
    cudaGetSymbolAddress((void**)&p_x1lo, g_x1lo);
    cudaGetSymbolAddress((void**)&p_h1hi, g_h1hi);
    cudaGetSymbolAddress((void**)&p_h1lo, g_h1lo);
    cudaGetSymbolAddress((void**)&p_x2hi, g_x2hi);
    cudaGetSymbolAddress((void**)&p_x2lo, g_x2lo);
    cudaGetSymbolAddress((void**)&p_h2, g_h2);
    cudaGetSymbolAddress((void**)&p_awraw, g_awraw);

    const int SMEM1 = (4 * 128 * KP1 + 4 * 64 * KP1) * 2;
    const int SMEM2 = (4 * 128 * KP2 + 4 * 64 * KP2) * 2;
    cudaFuncSetAttribute(k_mma_gemm<KC1, KP1, 0>, cudaFuncAttributeMaxDynamicSharedMemorySize, SMEM1);
    cudaFuncSetAttribute(k_mma_gemm<KC2, KP2, 1>, cudaFuncAttributeMaxDynamicSharedMemorySize, SMEM2);

    int tb = 256;
    int gN = (N + tb - 1) / tb;
    int gE = (E + tb - 1) / tb;
    int gW = (N + 7) / 8;
    int nScanBlk = (N + SCAN_TPB - 1) / SCAN_TPB;
    int ntiles = (N + 63) / 64;
    int gGemm = (ntiles < 148) ? ntiles : 148;

    // 0. conversions
    k_convw<<<(2 * 128 * KP1 + tb - 1) / tb, tb>>>(W1, Wr1, 74, KP1, p_wt);
    k_convw<<<(2 * 128 * KP2 + tb - 1) / tb, tb>>>(W2, Wr2, 128, KP2, p_wt + 4 * WSEG1);
    k_convY1<<<(N * (KC1 / 2) + tb - 1) / tb, tb>>>(node_feats, N);

    // 1. degrees + norms + CSR
    k_zero3<<<gN, tb>>>(N);
    k_deg<<<gE, tb>>>(src, dst, E);
    k_scan1<<<nScanBlk, SCAN_TPB>>>(N);
    k_scan2<<<1, 1024>>>(nScanBlk, N, E);
    k_scan3<<<nScanBlk, SCAN_TPB>>>(N);
    k_fill_csr<<<gE, tb>>>(src, dst, E);

    // 2. layer 1
    k_aggregate74<<<gW, tb>>>(node_feats, N);
    k_mma_gemm<KC1, KP1, 0><<<gGemm, 256, SMEM1>>>(
        p_x1hi, p_x1lo, p_y1hi, p_y1lo, p_wt, b1, br1,
        nullptr, p_h1hi, p_h1lo, nullptr, nullptr, N, ntiles);

    // 3. layer 2
    k_aggregate128<<<gW, tb>>>(N);
    k_mma_gemm<KC2, KP2, 1><<<gGemm, 256, SMEM2>>>(
        p_x2hi, p_x2lo, p_h1hi, p_h1lo, p_wt + 4 * WSEG1, b2, br2,
        p_h2, nullptr, nullptr, p_awraw, w_atom, N, ntiles);

    // 4. readout
    k_awfin<<<gN, tb>>>(b_atom, N);
    k_gbound<<<gN, tb>>>(graph_ids, N, G);
    k_readout<<<G, HID>>>(G);

    // 5. MLP head + output
    if (Kidx > 0) k_zero_rows<<<Kidx, DIM>>>(idx_wo, out);
    k_mlp1<<<(G + 7) / 8, HID>>>(Wp1, bp1, G);
    k_mlp2<<<(G + 7) / 8, DIM>>>(Wp2, bp2, idx_wo, Kidx, G, out);
}

// round 6
// speedup vs baseline: 3.1856x; 1.6317x over previous
#include <cuda_runtime.h>
#include <cuda_bf16.h>
#include <math.h>

// ---------------------------------------------------------------------------
// Drugemb R6: launch-count reduction (19 -> 11) + cp.async double-buffered
// persistent tensor-core dual-GEMMs.
//  - k_init: weight conv (both layers) + node-feat conv + zeroing + out zero-rows
//  - k_tail: sigmoid(aw) + graph bounds (binary search) + weighted-sum/max
//            readout + MLP1 + MLP2 + scatter, all in one kernel (smem staging)
//  - GEMMs: 2-stage cp.async pipeline; layer2 uses BM=32 to fit double buffers
// ---------------------------------------------------------------------------

#define NODE_F 74
#define HID 128
#define DIM 256

#define N_MAX 131072
#define E_MAX 524288
#define SCAN_TPB 1024

typedef unsigned int u32;
typedef __nv_bfloat16 bf16;

#define KC1 80
#define KC2 128
#define KP1 88
#define KP2 136
#define WSEG1 (128 * KP1)
#define WSEG2 (128 * KP2)

// ---- scratch ----
__device__ float g_norm_s[N_MAX];
__device__ float g_norm_d[N_MAX];
__device__ int   g_outdeg[N_MAX];
__device__ int   g_indeg[N_MAX];
__device__ int   g_fill[N_MAX];
__device__ int   g_rowptr[N_MAX + 1];
__device__ int   g_blksum[N_MAX / SCAN_TPB + 2];
__device__ int   g_csr_src[E_MAX];
__device__ __align__(16) bf16  g_y1hi[(size_t)N_MAX * KC1];
__device__ __align__(16) bf16  g_y1lo[(size_t)N_MAX * KC1];
__device__ __align__(16) bf16  g_x1hi[(size_t)N_MAX * KC1];
__device__ __align__(16) bf16  g_x1lo[(size_t)N_MAX * KC1];
__device__ __align__(16) bf16  g_h1hi[(size_t)N_MAX * HID];
__device__ __align__(16) bf16  g_h1lo[(size_t)N_MAX * HID];
__device__ __align__(16) bf16  g_x2hi[(size_t)N_MAX * HID];
__device__ __align__(16) bf16  g_x2lo[(size_t)N_MAX * HID];
__device__ __align__(16) float g_h2[(size_t)N_MAX * HID];
__device__ float g_awraw[N_MAX];
__device__ __align__(16) bf16  g_wt[4 * WSEG1 + 4 * WSEG2];

__device__ __forceinline__ void split_bf16(float v, bf16& h, bf16& l) {
    h = __float2bfloat16_rn(v);
    l = __float2bfloat16_rn(v - __bfloat162float(h));
}

__device__ __forceinline__ void cp16(bf16* s, const bf16* g) {
    u32 sa = (u32)__cvta_generic_to_shared(s);
    asm volatile("cp.async.ca.shared.global [%0], [%1], 16;" :: "r"(sa), "l"(g));
}

// ---------------------------------------------------------------------------
// k_init: all independent setup in one launch.
// regions: [convw L1][convw L2][convY1][zero N][zero out rows]
__global__ void k_init(const float* __restrict__ W1, const float* __restrict__ Wr1,
                       const float* __restrict__ W2, const float* __restrict__ Wr2,
                       const float* __restrict__ nf, const int* __restrict__ idxwo,
                       float* __restrict__ out, int n, int Kidx) {
    int i = blockIdx.x * blockDim.x + threadIdx.x;
    const int nA = 2 * 128 * KP1;
    const int nB = 2 * 128 * KP2;
    const int nC = n * (KC1 / 2);
    if (i < nA) {
        const int seg = 128 * KP1;
        const float* S = (i < seg) ? W1 : Wr1;
        bf16* hi = (i < seg) ? g_wt : g_wt + 2 * seg;
        bf16* lo = hi + seg;
        int j = (i < seg) ? i : i - seg;
        int nn = j / KP1, k = j - nn * KP1;
        float v = (k < NODE_F) ? S[k * 128 + nn] : 0.0f;
        bf16 h, l; split_bf16(v, h, l);
        hi[j] = h; lo[j] = l;
        return;
    }
    i -= nA;
    if (i < nB) {
        const int seg = 128 * KP2;
        const float* S = (i < seg) ? W2 : Wr2;
        bf16* hi = (i < seg) ? g_wt + 4 * WSEG1 : g_wt + 4 * WSEG1 + 2 * seg;
        bf16* lo = hi + seg;
        int j = (i < seg) ? i : i - seg;
        int nn = j / KP2, k = j - nn * KP2;
        float v = (k < HID) ? S[k * 128 + nn] : 0.0f;
        bf16 h, l; split_bf16(v, h, l);
        hi[j] = h; lo[j] = l;
        return;
    }
    i -= nB;
    if (i < nC) {
        int row = i / (KC1 / 2);
        int col = (i - row * (KC1 / 2)) * 2;
        float v0 = 0.0f, v1 = 0.0f;
        if (col < NODE_F - 1) {
            float2 t = *(const float2*)(nf + (size_t)row * NODE_F + col);
            v0 = t.x; v1 = t.y;
        }
        bf16 h0, l0, h1, l1;
        split_bf16(v0, h0, l0);
        split_bf16(v1, h1, l1);
        size_t o = (size_t)row * KC1 + col;
        *(__nv_bfloat162*)(g_y1hi + o) = __nv_bfloat162(h0, h1);
        *(__nv_bfloat162*)(g_y1lo + o) = __nv_bfloat162(l0, l1);
        return;
    }
    i -= nC;
    if (i < n) {
        g_outdeg[i] = 0; g_indeg[i] = 0; g_fill[i] = 0; g_awraw[i] = 0.0f;
        return;
    }
    i -= n;
    if (i < Kidx * DIM) {
        int r = idxwo[i / DIM];
        out[(size_t)r * DIM + (i % DIM)] = 0.0f;
    }
}

__global__ void k_deg(const int* __restrict__ src, const int* __restrict__ dst, int E) {
    int e = blockIdx.x * blockDim.x + threadIdx.x;
    if (e < E) {
        atomicAdd(&g_outdeg[src[e]], 1);
        atomicAdd(&g_indeg[dst[e]], 1);
    }
}

// ---- scan (+ fused norm computation) ----
__global__ void k_scan1(int n) {
    __shared__ int wsum[32];
    int tid = threadIdx.x, lane = tid & 31, warp = tid >> 5;
    int i = blockIdx.x * SCAN_TPB + tid;
    int v = (i < n) ? g_indeg[i] : 0;
    if (i < n) g_norm_d[i] = rsqrtf(fmaxf((float)v, 1.0f));
    int x = v;
    #pragma unroll
    for (int o = 1; o < 32; o <<= 1) {
        int t = __shfl_up_sync(0xffffffffu, x, o);
        if (lane >= o) x += t;
    }
    if (lane == 31) wsum[warp] = x;
    __syncthreads();
    if (warp == 0) {
        int s2 = wsum[lane];
        int y = s2;
        #pragma unroll
        for (int o = 1; o < 32; o <<= 1) {
            int t = __shfl_up_sync(0xffffffffu, y, o);
            if (lane >= o) y += t;
        }
        wsum[lane] = y - s2;
    }
    __syncthreads();
    int incl = x + wsum[warp];
    if (i < n) g_rowptr[i] = incl - v;
    if (tid == SCAN_TPB - 1) g_blksum[blockIdx.x] = incl;
}

__global__ void k_scan2(int nblk, int n, int e_total) {
    __shared__ int wsum[32];
    int tid = threadIdx.x, lane = tid & 31, warp = tid >> 5;
    int v = (tid < nblk) ? g_blksum[tid] : 0;
    int x = v;
    #pragma unroll
    for (int o = 1; o < 32; o <<= 1) {
        int t = __shfl_up_sync(0xffffffffu, x, o);
        if (lane >= o) x += t;
    }
    if (lane == 31) wsum[warp] = x;
    __syncthreads();
    if (warp == 0) {
        int s2 = wsum[lane];
        int y = s2;
        #pragma unroll
        for (int o = 1; o < 32; o <<= 1) {
            int t = __shfl_up_sync(0xffffffffu, y, o);
            if (lane >= o) y += t;
        }
        wsum[lane] = y - s2;
    }
    __syncthreads();
    if (tid < nblk) g_blksum[tid] = x + wsum[warp] - v;
    if (tid == 0) g_rowptr[n] = e_total;
}

__global__ void k_scan3(int n) {
    int i = blockIdx.x * SCAN_TPB + threadIdx.x;
    if (i < n) {
        g_rowptr[i] += g_blksum[blockIdx.x];
        g_norm_s[i] = rsqrtf(fmaxf((float)g_outdeg[i], 1.0f));
    }
}

__global__ void k_fill_csr(const int* __restrict__ src, const int* __restrict__ dst, int E) {
    int e = blockIdx.x * blockDim.x + threadIdx.x;
    if (e < E) {
        int d = dst[e];
        int pos = g_rowptr[d] + atomicAdd(&g_fill[d], 1);
        g_csr_src[pos] = src[e];
    }
}

// warp-per-node aggregation of node_feats -> X1 planes
__global__ void k_aggregate74(const float* __restrict__ hin, int n) {
    int w = (blockIdx.x * blockDim.x + threadIdx.x) >> 5;
    int lane = threadIdx.x & 31;
    if (w >= n) return;
    float a0 = 0.0f, a1 = 0.0f, a2 = 0.0f;
    int e0 = g_rowptr[w], e1 = g_rowptr[w + 1];
    for (int e = e0; e < e1; e++) {
        int s = g_csr_src[e];
        float ns = g_norm_s[s];
        const float* row = hin + (size_t)s * NODE_F;
        a0 += ns * __ldg(&row[lane]);
        a1 += ns * __ldg(&row[lane + 32]);
        if (lane < NODE_F - 64) a2 += ns * __ldg(&row[lane + 64]);
    }
    float nd = g_norm_d[w];
    size_t o = (size_t)w * KC1;
    bf16 h, l;
    split_bf16(a0 * nd, h, l);
    g_x1hi[o + lane] = h; g_x1lo[o + lane] = l;
    split_bf16(a1 * nd, h, l);
    g_x1hi[o + lane + 32] = h; g_x1lo[o + lane + 32] = l;
    if (lane < 16) {
        float v2 = (lane < NODE_F - 64) ? a2 * nd : 0.0f;
        split_bf16(v2, h, l);
        g_x1hi[o + lane + 64] = h; g_x1lo[o + lane + 64] = l;
    }
}

// warp-per-node aggregation of H1 planes -> X2 planes
__global__ void k_aggregate128(int n) {
    int w = (blockIdx.x * blockDim.x + threadIdx.x) >> 5;
    int lane = threadIdx.x & 31;
    if (w >= n) return;
    float acc0 = 0.f, acc1 = 0.f, acc2 = 0.f, acc3 = 0.f;
    int e0 = g_rowptr[w], e1 = g_rowptr[w + 1];
    for (int e = e0; e < e1; e++) {
        int s = g_csr_src[e];
        float ns = g_norm_s[s];
        size_t o = (size_t)s * HID + lane * 4;
        __nv_bfloat162 h01 = *(const __nv_bfloat162*)(g_h1hi + o);
        __nv_bfloat162 h23 = *(const __nv_bfloat162*)(g_h1hi + o + 2);
        __nv_bfloat162 l01 = *(const __nv_bfloat162*)(g_h1lo + o);
        __nv_bfloat162 l23 = *(const __nv_bfloat162*)(g_h1lo + o + 2);
        float2 fh01 = __bfloat1622float2(h01), fh23 = __bfloat1622float2(h23);
        float2 fl01 = __bfloat1622float2(l01), fl23 = __bfloat1622float2(l23);
        acc0 += ns * (fh01.x + fl01.x);
        acc1 += ns * (fh01.y + fl01.y);
        acc2 += ns * (fh23.x + fl23.x);
        acc3 += ns * (fh23.y + fl23.y);
    }
    float nd = g_norm_d[w];
    bf16 h0, l0, h1, l1, h2, l2, h3, l3;
    split_bf16(acc0 * nd, h0, l0);
    split_bf16(acc1 * nd, h1, l1);
    split_bf16(acc2 * nd, h2, l2);
    split_bf16(acc3 * nd, h3, l3);
    size_t o = (size_t)w * HID + lane * 4;
    *(__nv_bfloat162*)(g_x2hi + o) = __nv_bfloat162(h0, h1);
    *(__nv_bfloat162*)(g_x2hi + o + 2) = __nv_bfloat162(h2, h3);
    *(__nv_bfloat162*)(g_x2lo + o) = __nv_bfloat162(l0, l1);
    *(__nv_bfloat162*)(g_x2lo + o + 2) = __nv_bfloat162(l2, l3);
}

// ---- persistent double-buffered tensor-core dual GEMM ----
__device__ __forceinline__ void mma16816(float* c, const u32* a, const u32* b) {
    asm volatile(
        "mma.sync.aligned.m16n8k16.row.col.f32.bf16.bf16.f32 "
        "{%0,%1,%2,%3}, {%4,%5,%6,%7}, {%8,%9}, {%0,%1,%2,%3};"
        : "+f"(c[0]), "+f"(c[1]), "+f"(c[2]), "+f"(c[3])
        : "r"(a[0]), "r"(a[1]), "r"(a[2]), "r"(a[3]), "r"(b[0]), "r"(b[1]));
}

// MODE 0: bf16 hi/lo plane output. MODE 1: fp32 output + fused w_atom dot.
template <int KC, int Kp, int BM, int MODE>
__global__ void __launch_bounds__(256, 1)
k_mma_gemm(const bf16* __restrict__ Xhi, const bf16* __restrict__ Xlo,
           const bf16* __restrict__ Yhi, const bf16* __restrict__ Ylo,
           const bf16* __restrict__ wbase,
           const float* __restrict__ b, const float* __restrict__ br,
           float* __restrict__ OutF, bf16* __restrict__ OutHi, bf16* __restrict__ OutLo,
           float* __restrict__ awraw, const float* __restrict__ w_atom,
           int n, int ntiles) {
    extern __shared__ char sm_raw[];
    bf16* smb = (bf16*)sm_raw;
    int tid = threadIdx.x;

    // weights -> smem once
    {
        const uint4* gsrc = (const uint4*)wbase;
        uint4* sdst = (uint4*)smb;
        const int n16 = 4 * 128 * Kp / 8;
        for (int i = tid; i < n16; i += 256) sdst[i] = gsrc[i];
    }

    constexpr int WN = (BM == 64) ? 2 : 4;     // warps along N
    constexpr int JN = (BM == 64) ? 8 : 4;     // 8-col groups per warp
    constexpr int CPR = KC / 8;                // uint4 per plane-row
    constexpr int TILE_ELEMS = BM * Kp;        // bf16 per plane
    const int WBASE = 4 * 128 * Kp;            // bf16 offset of tile buffers

    // tile loader (cp.async), buf in {0,1}
    auto load_tile = [&](int tile, int buf) {
        bf16* tb = smb + WBASE + buf * 4 * TILE_ELEMS;
        int row0 = tile * BM;
        for (int i = tid; i < BM * CPR; i += 256) {
            int r = i / CPR, cc = i - r * CPR;
            int gr = row0 + r;
            if (gr > n - 1) gr = n - 1;  // clamp; garbage rows masked in epilogue
            size_t go = (size_t)gr * KC + cc * 8;
            int so = r * Kp + cc * 8;
            cp16(tb + so, Xhi + go);
            cp16(tb + TILE_ELEMS + so, Xlo + go);
            cp16(tb + 2 * TILE_ELEMS + so, Yhi + go);
            cp16(tb + 3 * TILE_ELEMS + so, Ylo + go);
        }
        asm volatile("cp.async.commit_group;");
    };

    const u32* uS = (const u32*)sm_raw;
    const int KW = Kp / 2;
    const int W0 = 0;
    const int W1 = 64 * Kp;
    const int R0 = 128 * Kp;
    const int R1 = 192 * Kp;

    int lane = tid & 31, warp = tid >> 5;
    int wm = warp / WN;
    int wn = warp % WN;
    int g = lane >> 2, t = lane & 3;
    const int rowA = (wm * 16 + g) * KW;
    constexpr int KSTEPS = KC / 16;

    // tile-invariant epilogue constants
    float bj0[JN], bj1[JN], qj0[JN], qj1[JN], wa0[JN], wa1[JN];
    #pragma unroll
    for (int j = 0; j < JN; j++) {
        int c = wn * (JN * 8) + j * 8 + 2 * t;
        bj0[j] = __ldg(&b[c]);  bj1[j] = __ldg(&b[c + 1]);
        qj0[j] = __ldg(&br[c]); qj1[j] = __ldg(&br[c + 1]);
        if (MODE == 1) { wa0[j] = __ldg(&w_atom[c]); wa1[j] = __ldg(&w_atom[c + 1]); }
    }

    int buf = 0;
    load_tile(blockIdx.x, 0);

    for (int tile = blockIdx.x; tile < ntiles; tile += gridDim.x) {
        int nxt = tile + gridDim.x;
        if (nxt < ntiles) {
            load_tile(nxt, buf ^ 1);
            asm volatile("cp.async.wait_group 1;");
        } else {
            asm volatile("cp.async.wait_group 0;");
        }
        __syncthreads();

        const int TB = (WBASE + buf * 4 * TILE_ELEMS) / 2;  // word offset
        const int XH = TB;
        const int XL = TB + TILE_ELEMS / 2;
        const int YH = TB + TILE_ELEMS;
        const int YL = TB + 3 * TILE_ELEMS / 2;

        float acc1[JN][4], acc2[JN][4];
        #pragma unroll
        for (int j = 0; j < JN; j++)
            #pragma unroll
            for (int q = 0; q < 4; q++) { acc1[j][q] = 0.0f; acc2[j][q] = 0.0f; }

        #pragma unroll
        for (int kt = 0; kt < KSTEPS; kt++) {
            const int ko = kt * 8 + t;
            u32 xh[4], xl[4], yh[4], yl[4];
            xh[0] = uS[XH + rowA + ko];          xh[1] = uS[XH + rowA + 4 * Kp + ko];
            xh[2] = uS[XH + rowA + ko + 4];      xh[3] = uS[XH + rowA + 4 * Kp + ko + 4];
            xl[0] = uS[XL + rowA + ko];          xl[1] = uS[XL + rowA + 4 * Kp + ko];
            xl[2] = uS[XL + rowA + ko + 4];      xl[3] = uS[XL + rowA + 4 * Kp + ko + 4];
            yh[0] = uS[YH + rowA + ko];          yh[1] = uS[YH + rowA + 4 * Kp + ko];
            yh[2] = uS[YH + rowA + ko + 4];      yh[3] = uS[YH + rowA + 4 * Kp + ko + 4];
            yl[0] = uS[YL + rowA + ko];          yl[1] = uS[YL + rowA + 4 * Kp + ko];
            yl[2] = uS[YL + rowA + ko + 4];      yl[3] = uS[YL + rowA + 4 * Kp + ko + 4];

            #pragma unroll
            for (int j = 0; j < JN; j++) {
                const int colB = (wn * (JN * 8) + j * 8 + g) * KW + ko;
                u32 wh[2], wl[2], rh[2], rl[2];
                wh[0] = uS[W0 + colB]; wh[1] = uS[W0 + colB + 4];
                wl[0] = uS[W1 + colB]; wl[1] = uS[W1 + colB + 4];
                rh[0] = uS[R0 + colB]; rh[1] = uS[R0 + colB + 4];
                rl[0] = uS[R1 + colB]; rl[1] = uS[R1 + colB + 4];
                mma16816(acc1[j], xh, wh);
                mma16816(acc1[j], xh, wl);
                mma16816(acc1[j], xl, wh);
                mma16816(acc2[j], yh, rh);
                mma16816(acc2[j], yh, rl);
                mma16816(acc2[j], yl, rh);
            }
        }

        int row0 = tile * BM;
        int r0 = row0 + wm * 16 + g;
        int r1 = r0 + 8;
        float s0 = 0.0f, s1 = 0.0f;
        #pragma unroll
        for (int j = 0; j < JN; j++) {
            int c = wn * (JN * 8) + j * 8 + 2 * t;
            float v00 = fmaxf(acc1[j][0] + bj0[j], 0.0f) + fmaxf(acc2[j][0] + qj0[j], 0.0f);
            float v01 = fmaxf(acc1[j][1] + bj1[j], 0.0f) + fmaxf(acc2[j][1] + qj1[j], 0.0f);
            float v10 = fmaxf(acc1[j][2] + bj0[j], 0.0f) + fmaxf(acc2[j][2] + qj0[j], 0.0f);
            float v11 = fmaxf(acc1[j][3] + bj1[j], 0.0f) + fmaxf(acc2[j][3] + qj1[j], 0.0f);
            if (MODE == 0) {
                if (r0 < n) {
                    bf16 h0, l0, h1, l1;
                    split_bf16(v00, h0, l0); split_bf16(v01, h1, l1);
                    size_t o = (size_t)r0 * HID + c;
                    *(__nv_bfloat162*)(OutHi + o) = __nv_bfloat162(h0, h1);
                    *(__nv_bfloat162*)(OutLo + o) = __nv_bfloat162(l0, l1);
                }
                if (r1 < n) {
                    bf16 h0, l0, h1, l1;
                    split_bf16(v10, h0, l0); split_bf16(v11, h1, l1);
                    size_t o = (size_t)r1 * HID + c;
                    *(__nv_bfloat162*)(OutHi + o) = __nv_bfloat162(h0, h1);
                    *(__nv_bfloat162*)(OutLo + o) = __nv_bfloat162(l0, l1);
                }
            } else {
                if (r0 < n) *(float2*)(OutF + (size_t)r0 * HID + c) = make_float2(v00, v01);
                if (r1 < n) *(float2*)(OutF + (size_t)r1 * HID + c) = make_float2(v10, v11);
                s0 += v00 * wa0[j] + v01 * wa1[j];
                s1 += v10 * wa0[j] + v11 * wa1[j];
            }
        }
        if (MODE == 1) {
            s0 += __shfl_xor_sync(0xffffffffu, s0, 1);
            s0 += __shfl_xor_sync(0xffffffffu, s0, 2);
            s1 += __shfl_xor_sync(0xffffffffu, s1, 1);
            s1 += __shfl_xor_sync(0xffffffffu, s1, 2);
            if (t == 0) {
                if (r0 < n) atomicAdd(&awraw[r0], s0);
                if (r1 < n) atomicAdd(&awraw[r1], s1);
            }
        }
        __syncthreads();
        buf ^= 1;
    }
}

// ---------------------------------------------------------------------------
// k_tail: fused sigmoid + graph bounds + weighted-sum/max readout + MLP1 +
// MLP2 + scatter. 8 graphs per block, 256 threads.
__global__ void __launch_bounds__(256)
k_tail(const int* __restrict__ gid, const float* __restrict__ ba,
       const float* __restrict__ Wp1, const float* __restrict__ bp1,
       const float* __restrict__ Wp2, const float* __restrict__ bp2,
       const int* __restrict__ idxwo, int Kidx, int n, int G,
       float* __restrict__ out) {
    __shared__ float gf[8][2 * HID];
    __shared__ float hid[8][HID];
    __shared__ int sb[9];
    int tid = threadIdx.x;
    int g0 = blockIdx.x * 8;

    if (tid < 9) {
        int target = g0 + tid;
        int lo = 0, hi = n;
        while (lo < hi) {
            int m = (lo + hi) >> 1;
            if (__ldg(&gid[m]) < target) lo = m + 1; else hi = m;
        }
        sb[tid] = lo;
    }
    __syncthreads();

    int warp = tid >> 5, lane = tid & 31;
    int gg = g0 + warp;
    if (gg < G) {
        int s = sb[warp], e = sb[warp + 1];
        float batom = __ldg(&ba[0]);
        float4 sum = make_float4(0.f, 0.f, 0.f, 0.f);
        float4 mx = make_float4(-3.4e38f, -3.4e38f, -3.4e38f, -3.4e38f);
        for (int i = s; i < e; i++) {
            float aw = 1.0f / (1.0f + expf(-(g_awraw[i] + batom)));
            float4 v = *(const float4*)(g_h2 + (size_t)i * HID + lane * 4);
            sum.x += aw * v.x; sum.y += aw * v.y; sum.z += aw * v.z; sum.w += aw * v.w;
            mx.x = fmaxf(mx.x, v.x); mx.y = fmaxf(mx.y, v.y);
            mx.z = fmaxf(mx.z, v.z); mx.w = fmaxf(mx.w, v.w);
        }
        *(float4*)(&gf[warp][lane * 4]) = sum;
        *(float4*)(&gf[warp][HID + lane * 4]) = mx;
    }
    __syncthreads();

    // MLP1: relu(gfeat @ Wp1 + bp1). 256 threads = 128 cols x 2 j-halves.
    {
        int col = tid & 127, jb = (tid >> 7) * 4;
        float acc[4] = {0.f, 0.f, 0.f, 0.f};
        for (int k = 0; k < 2 * HID; k++) {
            float w = __ldg(&Wp1[k * HID + col]);
            #pragma unroll
            for (int j = 0; j < 4; j++) acc[j] += gf[jb + j][k] * w;
        }
        float bb = __ldg(&bp1[col]);
        #pragma unroll
        for (int j = 0; j < 4; j++) hid[jb + j][col] = fmaxf(acc[j] + bb, 0.0f);
    }
    __syncthreads();

    // MLP2: hidden @ Wp2 + bp2 -> out (remapped rows)
    {
        float acc[8];
        #pragma unroll
        for (int j = 0; j < 8; j++) acc[j] = 0.0f;
        for (int k = 0; k < HID; k++) {
            float w = __ldg(&Wp2[k * DIM + tid]);
            #pragma unroll
            for (int j = 0; j < 8; j++) acc[j] += hid[j][k] * w;
        }
        float bb = __ldg(&bp2[tid]);
        #pragma unroll
        for (int j = 0; j < 8; j++) {
            int gg2 = g0 + j;
            if (gg2 < G) {
                int p = gg2;
                for (int t2 = 0; t2 < Kidx; t2++) {
                    if (__ldg(&idxwo[t2]) <= p) p++;
                }
                out[(size_t)p * DIM + tid] = acc[j] + bb;
            }
        }
    }
}

// ---------------------------------------------------------------------------
extern "C" void kernel_launch(void* const* d_in, const int* in_sizes, int n_in,
                              void* d_out, int out_size) {
    const float* node_feats = (const float*)d_in[0];
    const float* W1  = (const float*)d_in[2];
    const float* b1  = (const float*)d_in[3];
    const float* Wr1 = (const float*)d_in[4];
    const float* br1 = (const float*)d_in[5];
    const float* W2  = (const float*)d_in[6];
    const float* b2  = (const float*)d_in[7];
    const float* Wr2 = (const float*)d_in[8];
    const float* br2 = (const float*)d_in[9];
    const float* w_atom = (const float*)d_in[10];
    const float* b_atom = (const float*)d_in[11];
    const float* Wp1 = (const float*)d_in[12];
    const float* bp1 = (const float*)d_in[13];
    const float* Wp2 = (const float*)d_in[14];
    const float* bp2 = (const float*)d_in[15];
    const int* src = (const int*)d_in[16];
    const int* dst = (const int*)d_in[17];
    const int* graph_ids = (const int*)d_in[18];
    const int* idx_wo = (const int*)d_in[19];
    float* out = (float*)d_out;

    int N = in_sizes[0] / NODE_F;
    int E = in_sizes[16];
    int Kidx = in_sizes[19];
    int total = out_size / DIM;
    int G = total - Kidx;

    bf16 *p_wt, *p_y1hi, *p_y1lo, *p_x1hi, *p_x1lo;
    bf16 *p_h1hi, *p_h1lo, *p_x2hi, *p_x2lo;
    float *p_h2, *p_awraw;
    cudaGetSymbolAddress((void**)&p_wt, g_wt);
    cudaGetSymbolAddress((void**)&p_y1hi, g_y1hi);
    cudaGetSymbolAddress((void**)&p_y1lo, g_y1lo);
    cudaGetSymbolAddress((void**)&p_x1hi, g_x1hi);
    cudaGetSymbolAddress((void**)&p_x1lo, g_x1lo);
    cudaGetSymbolAddress((void**)&p_h1hi, g_h1hi);
    cudaGetSymbolAddress((void**)&p_h1lo, g_h1lo);
    cudaGetSymbolAddress((void**)&p_x2hi, g_x2hi);
    cudaGetSymbolAddress((void**)&p_x2lo, g_x2lo);
    cudaGetSymbolAddress((void**)&p_h2, g_h2);
    cudaGetSymbolAddress((void**)&p_awraw, g_awraw);

    // smem: weights + 2 tile buffers
    const int SMEM1 = (4 * 128 * KP1 + 2 * 4 * 64 * KP1) * 2;   // 180224
    const int SMEM2 = (4 * 128 * KP2 + 2 * 4 * 32 * KP2) * 2;   // 208896
    cudaFuncSetAttribute(k_mma_gemm<KC1, KP1, 64, 0>, cudaFuncAttributeMaxDynamicSharedMemorySize, SMEM1);
    cudaFuncSetAttribute(k_mma_gemm<KC2, KP2, 32, 1>, cudaFuncAttributeMaxDynamicSharedMemorySize, SMEM2);

    int tb = 256;
    int gE = (E + tb - 1) / tb;
    int gW = (N + 7) / 8;
    int nScanBlk = (N + SCAN_TPB - 1) / SCAN_TPB;
    int ntiles1 = (N + 63) / 64;
    int ntiles2 = (N + 31) / 32;
    int gGemm1 = (ntiles1 < 148) ? ntiles1 : 148;
    int gGemm2 = (ntiles2 < 148) ? ntiles2 : 148;

    // 1. fused init
    int initWork = 2 * 128 * KP1 + 2 * 128 * KP2 + N * (KC1 / 2) + N + Kidx * DIM;
    k_init<<<(initWork + tb - 1) / tb, tb>>>(W1, Wr1, W2, Wr2, node_feats, idx_wo, out, N, Kidx);

    // 2. degrees + CSR
    k_deg<<<gE, tb>>>(src, dst, E);
    k_scan1<<<nScanBlk, SCAN_TPB>>>(N);
    k_scan2<<<1, 1024>>>(nScanBlk, N, E);
    k_scan3<<<nScanBlk, SCAN_TPB>>>(N);
    k_fill_csr<<<gE, tb>>>(src, dst, E);

    // 3. layer 1
    k_aggregate74<<<gW, tb>>>(node_feats, N);
    k_mma_gemm<KC1, KP1, 64, 0><<<gGemm1, 256, SMEM1>>>(
        p_x1hi, p_x1lo, p_y1hi, p_y1lo, p_wt, b1, br1,
        nullptr, p_h1hi, p_h1lo, nullptr, nullptr, N, ntiles1);

    // 4. layer 2
    k_aggregate128<<<gW, tb>>>(N);
    k_mma_gemm<KC2, KP2, 32, 1><<<gGemm2, 256, SMEM2>>>(
        p_x2hi, p_x2lo, p_h1hi, p_h1lo, p_wt + 4 * WSEG1, b2, br2,
        p_h2, nullptr, nullptr, p_awraw, w_atom, N, ntiles2);

    // 5. fused tail
    k_tail<<<(G + 7) / 8, 256>>>(graph_ids, b_atom, Wp1, bp1, Wp2, bp2,
                                 idx_wo, Kidx, N, G, out);
}